// round 1
// baseline (speedup 1.0000x reference)
#include <cuda_runtime.h>
#include <math.h>

#define NN    50000
#define FEAT  128
#define HID   256
#define K0    160        // layer-0 K (129) padded to multiple of 16
#define NE    800000
#define NSUB  512
#define SUBSZ 64
#define MTOT  (NSUB*SUBSZ)

// ---------------- scratch (device globals; no allocation allowed) ----------------
__device__ __align__(16) float g_H0 [NN*K0];     // [N,160] padded input features
__device__ __align__(16) float g_MSG[NN*HID];    // message buffer (reused; 160-col view for L0)
__device__ __align__(16) float g_HA [NN*HID];
__device__ __align__(16) float g_HB [NN*HID];
__device__ __align__(16) float g_W0p[K0*HID];    // zero-padded W0 [160,256]
__device__ __align__(16) float g_Z  [NSUB*4*HID];

__device__ __forceinline__ float* gbuf(int id){
    switch(id){
        case 0: return g_H0;
        case 1: return g_MSG;
        case 2: return g_HA;
        case 3: return g_HB;
        case 4: return g_W0p;
        default: return g_Z;
    }
}

// ---------------- setup kernels ----------------
__global__ void build_h0(const float* __restrict__ x){
    int idx = blockIdx.x*blockDim.x + threadIdx.x;
    const int total = NN*K0;
    for (; idx < total; idx += gridDim.x*blockDim.x){
        int i = idx / K0;
        int c = idx - i*K0;
        g_H0[idx] = (c < FEAT) ? x[i*FEAT + c] : 0.0f;   // col 128 (indicator) and pads start at 0
    }
}

__global__ void scatter_batch(const int* __restrict__ batches){
    int m = blockIdx.x*blockDim.x + threadIdx.x;
    if (m < MTOT) g_H0[(size_t)batches[m]*K0 + FEAT] = 1.0f;   // .at[batches].set(1.0)
}

__global__ void build_w0p(const float* __restrict__ W0){
    int idx = blockIdx.x*blockDim.x + threadIdx.x;
    if (idx < K0*HID){
        int r = idx / HID;
        int c = idx - r*HID;
        g_W0p[idx] = (r < FEAT+1) ? W0[r*HID + c] : 0.0f;
    }
}

__global__ void zero_msg4(int n4){
    float4 z = make_float4(0.f,0.f,0.f,0.f);
    int i = blockIdx.x*blockDim.x + threadIdx.x;
    for (; i < n4; i += gridDim.x*blockDim.x)
        ((float4*)g_MSG)[i] = z;
}

// ---------------- edge scatter: msg[dst] += w * h[src] ----------------
// one warp per edge; vectorized 16B reductions (red.global.add.v4.f32, sm_90+)
__global__ void edge_msg(int hsel,
                         const int*  __restrict__ src,
                         const int*  __restrict__ dst,
                         const float* __restrict__ ew,
                         int ld, int w4){
    const float* h = gbuf(hsel);
    int e = blockIdx.x*(blockDim.x >> 5) + (threadIdx.x >> 5);
    if (e >= NE) return;
    int lane = threadIdx.x & 31;
    int s = src[e];
    int d = dst[e];
    float wt = ew[e];
    const float4* hs = (const float4*)(h + (size_t)s*ld);
    float* md = g_MSG + (size_t)d*ld;
    for (int i = lane; i < w4; i += 32){
        float4 v = hs[i];
        float* p = md + i*4;
        asm volatile("red.global.add.v4.f32 [%0], {%1,%2,%3,%4};"
                     :: "l"(p), "f"(v.x*wt), "f"(v.y*wt), "f"(v.z*wt), "f"(v.w*wt)
                     : "memory");
    }
}

// ---------------- fused GIN layer GEMM: out = relu(((1+eps)*H + MSG) @ W + b) ----------------
// 64x64 tile, BK=16, 256 threads, 4x4 microtile per thread
template<int KPAD>
__global__ __launch_bounds__(256)
void gin_gemm(int hsel, const float* __restrict__ Wp, int wsel,
              const float* __restrict__ bias, const float* __restrict__ eps, int ei,
              int osel){
    const float* H   = gbuf(hsel);
    const float* MSG = g_MSG;
    const float* W   = (wsel >= 0) ? gbuf(wsel) : Wp;
    float* out = gbuf(osel);

    __shared__ float As[16][68];   // [k][m], padded
    __shared__ float Bs[16][64];   // [k][n]

    const int t  = threadIdx.x;
    const int bx = blockIdx.x, by = blockIdx.y;
    const int row0 = by*64, col0 = bx*64;

    const float ep = 1.0f + eps[ei];

    const int aRow = t >> 2,  aK   = (t & 3)  * 4;
    const int bRow = t >> 4,  bCol = (t & 15) * 4;
    const int ty   = t >> 4,  tx   = t & 15;

    float acc[4][4] = {};
    const int  gr  = row0 + aRow;
    const bool rok = (gr < NN);

    for (int k0 = 0; k0 < KPAD; k0 += 16){
        float4 va = make_float4(0.f,0.f,0.f,0.f);
        if (rok){
            const float4 hv = *(const float4*)(H   + (size_t)gr*KPAD + k0 + aK);
            const float4 mv = *(const float4*)(MSG + (size_t)gr*KPAD + k0 + aK);
            va.x = ep*hv.x + mv.x;  va.y = ep*hv.y + mv.y;
            va.z = ep*hv.z + mv.z;  va.w = ep*hv.w + mv.w;
        }
        As[aK+0][aRow] = va.x;
        As[aK+1][aRow] = va.y;
        As[aK+2][aRow] = va.z;
        As[aK+3][aRow] = va.w;

        *(float4*)&Bs[bRow][bCol] =
            *(const float4*)(W + (size_t)(k0 + bRow)*HID + col0 + bCol);

        __syncthreads();
        #pragma unroll
        for (int kk = 0; kk < 16; kk++){
            float4 a = *(const float4*)&As[kk][ty*4];
            float4 b = *(const float4*)&Bs[kk][tx*4];
            acc[0][0] += a.x*b.x; acc[0][1] += a.x*b.y; acc[0][2] += a.x*b.z; acc[0][3] += a.x*b.w;
            acc[1][0] += a.y*b.x; acc[1][1] += a.y*b.y; acc[1][2] += a.y*b.z; acc[1][3] += a.y*b.w;
            acc[2][0] += a.z*b.x; acc[2][1] += a.z*b.y; acc[2][2] += a.z*b.z; acc[2][3] += a.z*b.w;
            acc[3][0] += a.w*b.x; acc[3][1] += a.w*b.y; acc[3][2] += a.w*b.z; acc[3][3] += a.w*b.w;
        }
        __syncthreads();
    }

    const float4 bb = *(const float4*)(bias + col0 + tx*4);
    #pragma unroll
    for (int jm = 0; jm < 4; jm++){
        int r = row0 + ty*4 + jm;
        if (r < NN){
            float4 o;
            o.x = fmaxf(acc[jm][0] + bb.x, 0.f);
            o.y = fmaxf(acc[jm][1] + bb.y, 0.f);
            o.z = fmaxf(acc[jm][2] + bb.z, 0.f);
            o.w = fmaxf(acc[jm][3] + bb.w, 0.f);
            *(float4*)(out + (size_t)r*HID + col0 + tx*4) = o;
        }
    }
}

// ---------------- multipool: sum / mean / min / max over 64 nodes per subgraph ----------------
__global__ void pool_kernel(const int* __restrict__ batches){
    const float* h = g_HA;   // final layer output lives in g_HA
    __shared__ int idxs[SUBSZ];
    int t = threadIdx.x, b = blockIdx.x;
    if (t < SUBSZ) idxs[t] = batches[b*SUBSZ + t];
    __syncthreads();
    float s = 0.f, mn = 3.4e38f, mx = -3.4e38f;
    #pragma unroll 8
    for (int m = 0; m < SUBSZ; m++){
        float v = h[(size_t)idxs[m]*HID + t];
        s += v; mn = fminf(mn, v); mx = fmaxf(mx, v);
    }
    float* z = g_Z + (size_t)b*4*HID;
    z[t]         = s;
    z[HID + t]   = s * (1.0f/SUBSZ);   // segment count is exactly 64
    z[2*HID + t] = mn;
    z[3*HID + t] = mx;
}

// ---------------- readout + BCE loss ----------------
__global__ void zero_out(float* out){
    if (threadIdx.x == 0 && blockIdx.x == 0) out[0] = 0.f;
}

__global__ void readout(const float* __restrict__ Wr1, const float* __restrict__ br1,
                        const float* __restrict__ Wr2, const float* __restrict__ br2,
                        const float* __restrict__ labels, float* out){
    int b = blockIdx.x, t = threadIdx.x;
    __shared__ float z[4*HID];
    const float* zg = g_Z + (size_t)b*4*HID;
    for (int j = t; j < 4*HID; j += blockDim.x) z[j] = zg[j];
    __syncthreads();

    float acc = br1[t];
    #pragma unroll 4
    for (int k = 0; k < 4*HID; k += 4){
        float4 zz = *(const float4*)&z[k];
        acc += zz.x * Wr1[(size_t)(k+0)*HID + t];
        acc += zz.y * Wr1[(size_t)(k+1)*HID + t];
        acc += zz.z * Wr1[(size_t)(k+2)*HID + t];
        acc += zz.w * Wr1[(size_t)(k+3)*HID + t];
    }
    float hv = fmaxf(acc, 0.f) * Wr2[t];

    __shared__ float red[HID];
    red[t] = hv; __syncthreads();
    for (int sft = HID/2; sft > 0; sft >>= 1){
        if (t < sft) red[t] += red[t + sft];
        __syncthreads();
    }
    if (t == 0){
        float p = red[0] + br2[0];
        float l = labels[b];
        float term = fmaxf(p, 0.f) - p*l + log1pf(expf(-fabsf(p)));
        atomicAdd(out, term * (1.0f/NSUB));
    }
}

// ---------------- launch ----------------
extern "C" void kernel_launch(void* const* d_in, const int* in_sizes, int n_in,
                              void* d_out, int out_size){
    const float* x       = (const float*)d_in[0];
    const int*   esrc    = (const int*)  d_in[1];
    const int*   edst    = (const int*)  d_in[2];
    const float* ew      = (const float*)d_in[3];
    const int*   batches = (const int*)  d_in[4];
    /* d_in[5] segment_ids: structurally arange//64, unused */
    const float* labels  = (const float*)d_in[6];
    const float* W0      = (const float*)d_in[7];
    const float* b0      = (const float*)d_in[8];
    const float* W1      = (const float*)d_in[9];
    const float* b1      = (const float*)d_in[10];
    const float* W2      = (const float*)d_in[11];
    const float* b2      = (const float*)d_in[12];
    const float* eps     = (const float*)d_in[13];
    const float* Wr1     = (const float*)d_in[14];
    const float* br1     = (const float*)d_in[15];
    const float* Wr2     = (const float*)d_in[16];
    const float* br2     = (const float*)d_in[17];
    float* out = (float*)d_out;

    build_h0<<<4096, 256>>>(x);
    scatter_batch<<<(MTOT+255)/256, 256>>>(batches);
    build_w0p<<<(K0*HID+255)/256, 256>>>(W0);

    dim3 gemmGrid(HID/64, (NN+63)/64);

    // layer 0: K=160 (padded 129)
    zero_msg4<<<2048, 256>>>(NN*K0/4);
    edge_msg<<<NE/8, 256>>>(0, esrc, edst, ew, K0, 33 /* cover cols 0..131 */);
    gin_gemm<K0><<<gemmGrid, 256>>>(0, nullptr, 4, b0, eps, 0, 2);

    // layer 1
    zero_msg4<<<2048, 256>>>(NN*HID/4);
    edge_msg<<<NE/8, 256>>>(2, esrc, edst, ew, HID, HID/4);
    gin_gemm<HID><<<gemmGrid, 256>>>(2, W1, -1, b1, eps, 1, 3);

    // layer 2
    zero_msg4<<<2048, 256>>>(NN*HID/4);
    edge_msg<<<NE/8, 256>>>(3, esrc, edst, ew, HID, HID/4);
    gin_gemm<HID><<<gemmGrid, 256>>>(3, W2, -1, b2, eps, 2, 2);

    pool_kernel<<<NSUB, HID>>>(batches);
    zero_out<<<1, 32>>>(out);
    readout<<<NSUB, HID>>>(Wr1, br1, Wr2, br2, labels, out);
}

// round 2
// speedup vs baseline: 1.2384x; 1.2384x over previous
#include <cuda_runtime.h>
#include <cuda_bf16.h>
#include <math.h>
#include <stdint.h>

#define NN    50000
#define FEAT  128
#define HID   256
#define K0    160        // layer-0 K (129) padded to multiple of 16
#define NE    800000
#define NSUB  512
#define SUBSZ 64
#define MTOT  (NSUB*SUBSZ)

// ---------------- scratch (device globals; no allocation allowed) ----------------
__device__ __align__(16) float g_H0 [NN*K0];     // [N,160] padded input features
__device__ __align__(16) float g_MSG[NN*HID];    // message buffer (160-col view for L0)
__device__ __align__(16) float g_HA [NN*HID];
__device__ __align__(16) float g_HB [NN*HID];
__device__ __align__(16) float g_W0p[K0*HID];    // zero-padded W0 [160,256]
__device__ __align__(16) float g_Z  [NSUB*4*HID];

__device__ __forceinline__ float* gbuf(int id){
    switch(id){
        case 0: return g_H0;
        case 1: return g_MSG;
        case 2: return g_HA;
        case 3: return g_HB;
        case 4: return g_W0p;
        default: return g_Z;
    }
}

// ---------------- setup kernels ----------------
__global__ void build_h0(const float* __restrict__ x){
    int idx = blockIdx.x*blockDim.x + threadIdx.x;
    const int total = NN*K0;
    for (; idx < total; idx += gridDim.x*blockDim.x){
        int i = idx / K0;
        int c = idx - i*K0;
        g_H0[idx] = (c < FEAT) ? x[i*FEAT + c] : 0.0f;
    }
}

__global__ void scatter_batch(const int* __restrict__ batches){
    int m = blockIdx.x*blockDim.x + threadIdx.x;
    if (m < MTOT) g_H0[(size_t)batches[m]*K0 + FEAT] = 1.0f;
}

__global__ void build_w0p(const float* __restrict__ W0){
    int idx = blockIdx.x*blockDim.x + threadIdx.x;
    if (idx < K0*HID){
        int r = idx / HID;
        int c = idx - r*HID;
        g_W0p[idx] = (r < FEAT+1) ? W0[r*HID + c] : 0.0f;
    }
}

__global__ void zero_msg4(int n4){
    float4 z = make_float4(0.f,0.f,0.f,0.f);
    int i = blockIdx.x*blockDim.x + threadIdx.x;
    for (; i < n4; i += gridDim.x*blockDim.x)
        ((float4*)g_MSG)[i] = z;
}

// ---------------- edge scatter: msg[dst] += w * h[src] ----------------
__global__ void edge_msg(int hsel,
                         const int*  __restrict__ src,
                         const int*  __restrict__ dst,
                         const float* __restrict__ ew,
                         int ld, int w4){
    const float* h = gbuf(hsel);
    int e = blockIdx.x*(blockDim.x >> 5) + (threadIdx.x >> 5);
    if (e >= NE) return;
    int lane = threadIdx.x & 31;
    int s = src[e];
    int d = dst[e];
    float wt = ew[e];
    const float4* hs = (const float4*)(h + (size_t)s*ld);
    float* md = g_MSG + (size_t)d*ld;
    for (int i = lane; i < w4; i += 32){
        float4 v = hs[i];
        float* p = md + i*4;
        asm volatile("red.global.add.v4.f32 [%0], {%1,%2,%3,%4};"
                     :: "l"(p), "f"(v.x*wt), "f"(v.y*wt), "f"(v.z*wt), "f"(v.w*wt)
                     : "memory");
    }
}

// ---------------- tensor-core GIN GEMM: out = relu(((1+eps)*H + MSG) @ W + b) ------
// bf16 3-product split (ah*bh + ah*bl + al*bh) for fp32-grade accuracy.
// Block tile 128x128, BK=16, 8 warps (2x4), warp tile 64x32, m16n8k16 mma.

__device__ __forceinline__ uint32_t sptr(const void* p){
    return (uint32_t)__cvta_generic_to_shared(p);
}
__device__ __forceinline__ void ldsm4(uint32_t& r0,uint32_t& r1,uint32_t& r2,uint32_t& r3, uint32_t a){
    asm volatile("ldmatrix.sync.aligned.m8n8.x4.shared.b16 {%0,%1,%2,%3},[%4];"
                 : "=r"(r0),"=r"(r1),"=r"(r2),"=r"(r3) : "r"(a));
}
__device__ __forceinline__ void ldsm4t(uint32_t& r0,uint32_t& r1,uint32_t& r2,uint32_t& r3, uint32_t a){
    asm volatile("ldmatrix.sync.aligned.m8n8.x4.trans.shared.b16 {%0,%1,%2,%3},[%4];"
                 : "=r"(r0),"=r"(r1),"=r"(r2),"=r"(r3) : "r"(a));
}
__device__ __forceinline__ void mma16816(float* c, const uint32_t* a, uint32_t b0, uint32_t b1){
    asm volatile("mma.sync.aligned.m16n8k16.row.col.f32.bf16.bf16.f32 "
                 "{%0,%1,%2,%3},{%4,%5,%6,%7},{%8,%9},{%0,%1,%2,%3};"
                 : "+f"(c[0]),"+f"(c[1]),"+f"(c[2]),"+f"(c[3])
                 : "r"(a[0]),"r"(a[1]),"r"(a[2]),"r"(a[3]),"r"(b0),"r"(b1));
}
__device__ __forceinline__ uint32_t bpack(__nv_bfloat16 a, __nv_bfloat16 b){
    __nv_bfloat162 t = __halves2bfloat162(a,b);
    return *reinterpret_cast<uint32_t*>(&t);
}

#define ALD 24    // Ash row stride (bf16) — conflict-free LDSM
#define BLD 136   // Bsh row stride (bf16)

template<int K>
__global__ __launch_bounds__(256)
void gemm_mma(int hsel, const float* __restrict__ Wp, int wsel,
              const float* __restrict__ bias, const float* __restrict__ eps, int ei,
              int osel){
    const float* H   = gbuf(hsel);
    const float* MSG = g_MSG;
    const float* W   = (wsel >= 0) ? gbuf(wsel) : Wp;
    float* out = gbuf(osel);

    __shared__ __nv_bfloat16 Ash[2][128*ALD];
    __shared__ __nv_bfloat16 Asl[2][128*ALD];
    __shared__ __nv_bfloat16 Bsh[2][16*BLD];
    __shared__ __nv_bfloat16 Bsl[2][16*BLD];

    const int t = threadIdx.x;
    const int warp = t >> 5, lane = t & 31;
    const int wm = warp >> 2, wn = warp & 3;
    const int row0 = blockIdx.y*128, col0 = blockIdx.x*128;
    const float ep = 1.0f + eps[ei];

    float acc[4][4][4];
    #pragma unroll
    for (int i=0;i<4;i++)
        #pragma unroll
        for (int j=0;j<4;j++)
            #pragma unroll
            for (int q=0;q<4;q++) acc[i][j][q]=0.f;

    float aval[2][4];
    float bval[2][4];

    auto loadstage = [&](int ks){
        const int k0 = ks*16;
        #pragma unroll
        for (int s=0;s<2;s++){
            int idx = t + s*256;
            int r = idx >> 2, c4 = idx & 3;
            int gr = row0 + r;
            float4 hv = make_float4(0.f,0.f,0.f,0.f);
            float4 mv = make_float4(0.f,0.f,0.f,0.f);
            if (gr < NN){
                hv = *(const float4*)(H   + (size_t)gr*K + k0 + c4*4);
                mv = *(const float4*)(MSG + (size_t)gr*K + k0 + c4*4);
            }
            aval[s][0] = ep*hv.x + mv.x;
            aval[s][1] = ep*hv.y + mv.y;
            aval[s][2] = ep*hv.z + mv.z;
            aval[s][3] = ep*hv.w + mv.w;
        }
        #pragma unroll
        for (int s=0;s<2;s++){
            int idx = t + s*256;
            int r = idx >> 5, c4 = idx & 31;
            float4 wv = *(const float4*)(W + (size_t)(k0 + r)*HID + col0 + c4*4);
            bval[s][0]=wv.x; bval[s][1]=wv.y; bval[s][2]=wv.z; bval[s][3]=wv.w;
        }
    };

    auto storestage = [&](int buf){
        #pragma unroll
        for (int s=0;s<2;s++){
            int idx = t + s*256;
            int r = idx >> 2, c4 = idx & 3;
            __nv_bfloat16 h[4], l[4];
            #pragma unroll
            for (int j=0;j<4;j++){
                h[j] = __float2bfloat16(aval[s][j]);
                l[j] = __float2bfloat16(aval[s][j] - __bfloat162float(h[j]));
            }
            *(uint2*)&Ash[buf][r*ALD + c4*4] = make_uint2(bpack(h[0],h[1]), bpack(h[2],h[3]));
            *(uint2*)&Asl[buf][r*ALD + c4*4] = make_uint2(bpack(l[0],l[1]), bpack(l[2],l[3]));
        }
        #pragma unroll
        for (int s=0;s<2;s++){
            int idx = t + s*256;
            int r = idx >> 5, c4 = idx & 31;
            __nv_bfloat16 h[4], l[4];
            #pragma unroll
            for (int j=0;j<4;j++){
                h[j] = __float2bfloat16(bval[s][j]);
                l[j] = __float2bfloat16(bval[s][j] - __bfloat162float(h[j]));
            }
            *(uint2*)&Bsh[buf][r*BLD + c4*4] = make_uint2(bpack(h[0],h[1]), bpack(h[2],h[3]));
            *(uint2*)&Bsl[buf][r*BLD + c4*4] = make_uint2(bpack(l[0],l[1]), bpack(l[2],l[3]));
        }
    };

    auto compute = [&](int buf){
        // fragment addresses
        const int arow = wm*64 + (lane & 15);
        const int acol = (lane >> 4)*8;
        uint32_t aAddrH = sptr(&Ash[buf][0]) + (uint32_t)((arow*ALD + acol)*2);
        uint32_t aAddrL = sptr(&Asl[buf][0]) + (uint32_t)((arow*ALD + acol)*2);
        const int brow = lane & 15;
        const int bcol = wn*32 + (lane >> 4)*8;
        uint32_t bAddrH = sptr(&Bsh[buf][0]) + (uint32_t)((brow*BLD + bcol)*2);
        uint32_t bAddrL = sptr(&Bsl[buf][0]) + (uint32_t)((brow*BLD + bcol)*2);

        uint32_t A[4][4], B[4][2], Bl[4][2];
        #pragma unroll
        for (int mi=0; mi<4; mi++)
            ldsm4(A[mi][0],A[mi][1],A[mi][2],A[mi][3], aAddrH + (uint32_t)(mi*16*ALD*2));
        #pragma unroll
        for (int np=0; np<2; np++)
            ldsm4t(B[2*np][0],B[2*np][1],B[2*np+1][0],B[2*np+1][1],
                   bAddrH + (uint32_t)(np*16*2));
        #pragma unroll
        for (int np=0; np<2; np++)
            ldsm4t(Bl[2*np][0],Bl[2*np][1],Bl[2*np+1][0],Bl[2*np+1][1],
                   bAddrL + (uint32_t)(np*16*2));
        // hi*hi
        #pragma unroll
        for (int mi=0; mi<4; mi++)
            #pragma unroll
            for (int ni=0; ni<4; ni++)
                mma16816(acc[mi][ni], A[mi], B[ni][0], B[ni][1]);
        // hi*lo
        #pragma unroll
        for (int mi=0; mi<4; mi++)
            #pragma unroll
            for (int ni=0; ni<4; ni++)
                mma16816(acc[mi][ni], A[mi], Bl[ni][0], Bl[ni][1]);
        // lo*hi  (overwrite A with Alo)
        #pragma unroll
        for (int mi=0; mi<4; mi++)
            ldsm4(A[mi][0],A[mi][1],A[mi][2],A[mi][3], aAddrL + (uint32_t)(mi*16*ALD*2));
        #pragma unroll
        for (int mi=0; mi<4; mi++)
            #pragma unroll
            for (int ni=0; ni<4; ni++)
                mma16816(acc[mi][ni], A[mi], B[ni][0], B[ni][1]);
    };

    const int KS = K/16;
    loadstage(0);
    storestage(0);
    __syncthreads();
    for (int ks=0; ks<KS; ks++){
        if (ks+1 < KS) loadstage(ks+1);
        compute(ks & 1);
        if (ks+1 < KS) storestage((ks+1) & 1);
        __syncthreads();
    }

    // epilogue: bias + relu, f32 stores
    const int gid = lane >> 2, tig = lane & 3;
    #pragma unroll
    for (int ni=0; ni<4; ni++){
        int c = col0 + wn*32 + ni*8 + tig*2;
        float2 bb = *(const float2*)(bias + c);
        #pragma unroll
        for (int mi=0; mi<4; mi++){
            int r = row0 + wm*64 + mi*16 + gid;
            if (r < NN){
                float2 o;
                o.x = fmaxf(acc[mi][ni][0] + bb.x, 0.f);
                o.y = fmaxf(acc[mi][ni][1] + bb.y, 0.f);
                *(float2*)(out + (size_t)r*HID + c) = o;
            }
            int r2 = r + 8;
            if (r2 < NN){
                float2 o;
                o.x = fmaxf(acc[mi][ni][2] + bb.x, 0.f);
                o.y = fmaxf(acc[mi][ni][3] + bb.y, 0.f);
                *(float2*)(out + (size_t)r2*HID + c) = o;
            }
        }
    }
}

// ---------------- multipool ----------------
__global__ void pool_kernel(const int* __restrict__ batches){
    const float* h = g_HA;
    __shared__ int idxs[SUBSZ];
    int t = threadIdx.x, b = blockIdx.x;
    if (t < SUBSZ) idxs[t] = batches[b*SUBSZ + t];
    __syncthreads();
    float s = 0.f, mn = 3.4e38f, mx = -3.4e38f;
    #pragma unroll 8
    for (int m = 0; m < SUBSZ; m++){
        float v = h[(size_t)idxs[m]*HID + t];
        s += v; mn = fminf(mn, v); mx = fmaxf(mx, v);
    }
    float* z = g_Z + (size_t)b*4*HID;
    z[t]         = s;
    z[HID + t]   = s * (1.0f/SUBSZ);
    z[2*HID + t] = mn;
    z[3*HID + t] = mx;
}

// ---------------- readout (8 subgraphs per block) + BCE loss ----------------
__global__ void zero_out(float* out){
    if (threadIdx.x == 0 && blockIdx.x == 0) out[0] = 0.f;
}

__global__ __launch_bounds__(256)
void readout8(const float* __restrict__ Wr1, const float* __restrict__ br1,
              const float* __restrict__ Wr2, const float* __restrict__ br2,
              const float* __restrict__ labels, float* out){
    const int b0 = blockIdx.x*8;
    __shared__ float z[8*4*HID];   // 32KB
    int t = threadIdx.x;
    const float4* zg = (const float4*)(g_Z + (size_t)b0*4*HID);
    #pragma unroll
    for (int j = t; j < 8*4*HID/4; j += 256)
        ((float4*)z)[j] = zg[j];
    __syncthreads();

    float bb = br1[t];
    float acc[8];
    #pragma unroll
    for (int j=0;j<8;j++) acc[j] = bb;

    #pragma unroll 8
    for (int k=0;k<4*HID;k++){
        float w = Wr1[(size_t)k*HID + t];
        #pragma unroll
        for (int j=0;j<8;j++) acc[j] += z[j*4*HID + k]*w;
    }
    __syncthreads();
    float wr2 = Wr2[t];
    #pragma unroll
    for (int j=0;j<8;j++) z[j*HID + t] = fmaxf(acc[j], 0.f)*wr2;
    __syncthreads();

    int w = t >> 5, lane = t & 31;
    float s = 0.f;
    #pragma unroll
    for (int q=0;q<8;q++) s += z[w*HID + lane + q*32];
    #pragma unroll
    for (int off=16; off>0; off>>=1) s += __shfl_xor_sync(0xffffffffu, s, off);
    if (lane == 0){
        float p = s + br2[0];
        float l = labels[b0 + w];
        float term = fmaxf(p, 0.f) - p*l + log1pf(expf(-fabsf(p)));
        atomicAdd(out, term * (1.0f/NSUB));
    }
}

// ---------------- launch ----------------
extern "C" void kernel_launch(void* const* d_in, const int* in_sizes, int n_in,
                              void* d_out, int out_size){
    const float* x       = (const float*)d_in[0];
    const int*   esrc    = (const int*)  d_in[1];
    const int*   edst    = (const int*)  d_in[2];
    const float* ew      = (const float*)d_in[3];
    const int*   batches = (const int*)  d_in[4];
    const float* labels  = (const float*)d_in[6];
    const float* W0      = (const float*)d_in[7];
    const float* b0      = (const float*)d_in[8];
    const float* W1      = (const float*)d_in[9];
    const float* b1      = (const float*)d_in[10];
    const float* W2      = (const float*)d_in[11];
    const float* b2      = (const float*)d_in[12];
    const float* eps     = (const float*)d_in[13];
    const float* Wr1     = (const float*)d_in[14];
    const float* br1     = (const float*)d_in[15];
    const float* Wr2     = (const float*)d_in[16];
    const float* br2     = (const float*)d_in[17];
    float* out = (float*)d_out;

    build_h0<<<4096, 256>>>(x);
    scatter_batch<<<(MTOT+255)/256, 256>>>(batches);
    build_w0p<<<(K0*HID+255)/256, 256>>>(W0);

    dim3 gemmGrid(2, (NN+127)/128);

    // layer 0: K=160 (padded 129)
    zero_msg4<<<2048, 256>>>(NN*K0/4);
    edge_msg<<<NE/8, 256>>>(0, esrc, edst, ew, K0, 33);
    gemm_mma<K0><<<gemmGrid, 256>>>(0, nullptr, 4, b0, eps, 0, 2);

    // layer 1
    zero_msg4<<<2048, 256>>>(NN*HID/4);
    edge_msg<<<NE/8, 256>>>(2, esrc, edst, ew, HID, HID/4);
    gemm_mma<HID><<<gemmGrid, 256>>>(2, W1, -1, b1, eps, 1, 3);

    // layer 2
    zero_msg4<<<2048, 256>>>(NN*HID/4);
    edge_msg<<<NE/8, 256>>>(3, esrc, edst, ew, HID, HID/4);
    gemm_mma<HID><<<gemmGrid, 256>>>(3, W2, -1, b2, eps, 2, 2);

    pool_kernel<<<NSUB, HID>>>(batches);
    zero_out<<<1, 32>>>(out);
    readout8<<<NSUB/8, 256>>>(Wr1, br1, Wr2, br2, labels, out);
}

// round 3
// speedup vs baseline: 2.1064x; 1.7009x over previous
#include <cuda_runtime.h>
#include <cuda_bf16.h>
#include <math.h>
#include <stdint.h>

#define NN    50000
#define FEAT  128
#define HID   256
#define K0    160        // layer-0 K (129) padded to multiple of 16
#define NE    800000
#define NSUB  512
#define SUBSZ 64
#define MTOT  (NSUB*SUBSZ)

#define SCAN_B 256
#define NBLK   ((NN + SCAN_B - 1) / SCAN_B)   // 196

// ---------------- scratch (device globals; no allocation allowed) ----------------
__device__ __align__(16) float g_H0 [NN*K0];
__device__ __align__(16) float g_MSG[NN*HID];
__device__ __align__(16) float g_HA [NN*HID];
__device__ __align__(16) float g_HB [NN*HID];
__device__ __align__(16) float g_W0p[K0*HID];
__device__ __align__(16) float g_Z  [NSUB*4*HID];
// CSR scratch
__device__ int   g_deg [NN];
__device__ int   g_cur [NN];
__device__ int   g_off [NN+1];
__device__ int   g_bsum[NBLK];
__device__ int   g_csrc[NE];
__device__ float g_cw  [NE];

__device__ __forceinline__ float* gbuf(int id){
    switch(id){
        case 0: return g_H0;
        case 1: return g_MSG;
        case 2: return g_HA;
        case 3: return g_HB;
        case 4: return g_W0p;
        default: return g_Z;
    }
}

// ---------------- setup kernels ----------------
__global__ void build_h0(const float* __restrict__ x){
    int idx = blockIdx.x*blockDim.x + threadIdx.x;
    const int total = NN*K0;
    for (; idx < total; idx += gridDim.x*blockDim.x){
        int i = idx / K0;
        int c = idx - i*K0;
        g_H0[idx] = (c < FEAT) ? x[i*FEAT + c] : 0.0f;
    }
}

__global__ void scatter_batch(const int* __restrict__ batches){
    int m = blockIdx.x*blockDim.x + threadIdx.x;
    if (m < MTOT) g_H0[(size_t)batches[m]*K0 + FEAT] = 1.0f;
}

__global__ void build_w0p(const float* __restrict__ W0){
    int idx = blockIdx.x*blockDim.x + threadIdx.x;
    if (idx < K0*HID){
        int r = idx / HID;
        int c = idx - r*HID;
        g_W0p[idx] = (r < FEAT+1) ? W0[r*HID + c] : 0.0f;
    }
}

// ---------------- CSR build ----------------
__global__ void zero_degcur(){
    int i = blockIdx.x*blockDim.x + threadIdx.x;
    if (i < NN){ g_deg[i] = 0; g_cur[i] = 0; }
}

__global__ void hist_dst(const int* __restrict__ dst){
    int e = blockIdx.x*blockDim.x + threadIdx.x;
    if (e < NE) atomicAdd(&g_deg[dst[e]], 1);
}

// per-block exclusive scan of g_deg -> g_off, block totals -> g_bsum
__global__ void scan_block(){
    __shared__ int sh[SCAN_B];
    int i = blockIdx.x*SCAN_B + threadIdx.x;
    int v = (i < NN) ? g_deg[i] : 0;
    sh[threadIdx.x] = v;
    __syncthreads();
    // inclusive scan (Hillis-Steele)
    #pragma unroll
    for (int off = 1; off < SCAN_B; off <<= 1){
        int add = (threadIdx.x >= off) ? sh[threadIdx.x - off] : 0;
        __syncthreads();
        sh[threadIdx.x] += add;
        __syncthreads();
    }
    if (i < NN) g_off[i] = sh[threadIdx.x] - v;   // exclusive
    if (threadIdx.x == SCAN_B-1) g_bsum[blockIdx.x] = sh[SCAN_B-1];
}

__global__ void scan_bsums(){
    __shared__ int sh[256];
    int t = threadIdx.x;
    int v = (t < NBLK) ? g_bsum[t] : 0;
    sh[t] = v;
    __syncthreads();
    #pragma unroll
    for (int off = 1; off < 256; off <<= 1){
        int add = (t >= off) ? sh[t - off] : 0;
        __syncthreads();
        sh[t] += add;
        __syncthreads();
    }
    if (t < NBLK) g_bsum[t] = sh[t] - v;   // exclusive
}

__global__ void scan_add(){
    int i = blockIdx.x*SCAN_B + threadIdx.x;
    if (i < NN) g_off[i] += g_bsum[blockIdx.x];
    if (i == 0) g_off[NN] = NE;
}

__global__ void csr_scatter(const int* __restrict__ src, const int* __restrict__ dst,
                            const float* __restrict__ ew){
    int e = blockIdx.x*blockDim.x + threadIdx.x;
    if (e < NE){
        int d = dst[e];
        int pos = g_off[d] + atomicAdd(&g_cur[d], 1);
        g_csrc[pos] = src[e];
        g_cw[pos]   = ew[e];
    }
}

// ---------------- gather: MSG[n] = (1+eps)*h[n] + sum_{e: dst=n} w_e * h[src_e] ----
// one warp per node; register accumulation; single store per row.
__global__ __launch_bounds__(256)
void csr_gather(int hsel, const float* __restrict__ eps, int ei, int ld, int w4r, int w4p){
    const float* h = gbuf(hsel);
    int n = blockIdx.x*8 + (threadIdx.x >> 5);
    if (n >= NN) return;
    int lane = threadIdx.x & 31;
    int s0 = g_off[n], s1 = g_off[n+1];

    const bool a0 = (lane      < w4r);
    const bool a1 = (lane + 32 < w4r);
    float4 acc0 = make_float4(0.f,0.f,0.f,0.f);
    float4 acc1 = make_float4(0.f,0.f,0.f,0.f);

    for (int e = s0; e < s1; e++){
        int s   = __ldg(&g_csrc[e]);
        float w = __ldg(&g_cw[e]);
        const float4* hs = (const float4*)(h + (size_t)s*ld);
        if (a0){
            float4 v = hs[lane];
            acc0.x += w*v.x; acc0.y += w*v.y; acc0.z += w*v.z; acc0.w += w*v.w;
        }
        if (a1){
            float4 v = hs[lane+32];
            acc1.x += w*v.x; acc1.y += w*v.y; acc1.z += w*v.z; acc1.w += w*v.w;
        }
    }

    const float ep = 1.0f + eps[ei];
    const float4* hn = (const float4*)(h + (size_t)n*ld);
    float4* mrow = (float4*)(g_MSG + (size_t)n*ld);
    if (a0){
        float4 v = hn[lane];
        acc0.x += ep*v.x; acc0.y += ep*v.y; acc0.z += ep*v.z; acc0.w += ep*v.w;
        mrow[lane] = acc0;
    }
    if (a1){
        float4 v = hn[lane+32];
        acc1.x += ep*v.x; acc1.y += ep*v.y; acc1.z += ep*v.z; acc1.w += ep*v.w;
        mrow[lane+32] = acc1;
    } else if (lane + 32 < w4p){
        mrow[lane+32] = make_float4(0.f,0.f,0.f,0.f);   // zero pad cols
    }
}

// ---------------- tensor-core GIN GEMM: out = relu(MSG @ W + b) ------
// bf16 3-product split. Block tile 128x128, BK=16, 8 warps, warp tile 64x32.

__device__ __forceinline__ uint32_t sptr(const void* p){
    return (uint32_t)__cvta_generic_to_shared(p);
}
__device__ __forceinline__ void ldsm4(uint32_t& r0,uint32_t& r1,uint32_t& r2,uint32_t& r3, uint32_t a){
    asm volatile("ldmatrix.sync.aligned.m8n8.x4.shared.b16 {%0,%1,%2,%3},[%4];"
                 : "=r"(r0),"=r"(r1),"=r"(r2),"=r"(r3) : "r"(a));
}
__device__ __forceinline__ void ldsm4t(uint32_t& r0,uint32_t& r1,uint32_t& r2,uint32_t& r3, uint32_t a){
    asm volatile("ldmatrix.sync.aligned.m8n8.x4.trans.shared.b16 {%0,%1,%2,%3},[%4];"
                 : "=r"(r0),"=r"(r1),"=r"(r2),"=r"(r3) : "r"(a));
}
__device__ __forceinline__ void mma16816(float* c, const uint32_t* a, uint32_t b0, uint32_t b1){
    asm volatile("mma.sync.aligned.m16n8k16.row.col.f32.bf16.bf16.f32 "
                 "{%0,%1,%2,%3},{%4,%5,%6,%7},{%8,%9},{%0,%1,%2,%3};"
                 : "+f"(c[0]),"+f"(c[1]),"+f"(c[2]),"+f"(c[3])
                 : "r"(a[0]),"r"(a[1]),"r"(a[2]),"r"(a[3]),"r"(b0),"r"(b1));
}
__device__ __forceinline__ uint32_t bpack(__nv_bfloat16 a, __nv_bfloat16 b){
    __nv_bfloat162 t = __halves2bfloat162(a,b);
    return *reinterpret_cast<uint32_t*>(&t);
}

#define ALD 24
#define BLD 136

template<int K>
__global__ __launch_bounds__(256)
void gemm_mma(const float* __restrict__ Wp, int wsel,
              const float* __restrict__ bias, int osel){
    const float* A   = g_MSG;
    const float* W   = (wsel >= 0) ? gbuf(wsel) : Wp;
    float* out = gbuf(osel);

    __shared__ __nv_bfloat16 Ash[2][128*ALD];
    __shared__ __nv_bfloat16 Asl[2][128*ALD];
    __shared__ __nv_bfloat16 Bsh[2][16*BLD];
    __shared__ __nv_bfloat16 Bsl[2][16*BLD];

    const int t = threadIdx.x;
    const int warp = t >> 5, lane = t & 31;
    const int wm = warp >> 2, wn = warp & 3;
    const int row0 = blockIdx.y*128, col0 = blockIdx.x*128;

    float acc[4][4][4];
    #pragma unroll
    for (int i=0;i<4;i++)
        #pragma unroll
        for (int j=0;j<4;j++)
            #pragma unroll
            for (int q=0;q<4;q++) acc[i][j][q]=0.f;

    float aval[2][4];
    float bval[2][4];

    auto loadstage = [&](int ks){
        const int k0 = ks*16;
        #pragma unroll
        for (int s=0;s<2;s++){
            int idx = t + s*256;
            int r = idx >> 2, c4 = idx & 3;
            int gr = row0 + r;
            float4 mv = make_float4(0.f,0.f,0.f,0.f);
            if (gr < NN)
                mv = *(const float4*)(A + (size_t)gr*K + k0 + c4*4);
            aval[s][0]=mv.x; aval[s][1]=mv.y; aval[s][2]=mv.z; aval[s][3]=mv.w;
        }
        #pragma unroll
        for (int s=0;s<2;s++){
            int idx = t + s*256;
            int r = idx >> 5, c4 = idx & 31;
            float4 wv = *(const float4*)(W + (size_t)(k0 + r)*HID + col0 + c4*4);
            bval[s][0]=wv.x; bval[s][1]=wv.y; bval[s][2]=wv.z; bval[s][3]=wv.w;
        }
    };

    auto storestage = [&](int buf){
        #pragma unroll
        for (int s=0;s<2;s++){
            int idx = t + s*256;
            int r = idx >> 2, c4 = idx & 3;
            __nv_bfloat16 h[4], l[4];
            #pragma unroll
            for (int j=0;j<4;j++){
                h[j] = __float2bfloat16(aval[s][j]);
                l[j] = __float2bfloat16(aval[s][j] - __bfloat162float(h[j]));
            }
            *(uint2*)&Ash[buf][r*ALD + c4*4] = make_uint2(bpack(h[0],h[1]), bpack(h[2],h[3]));
            *(uint2*)&Asl[buf][r*ALD + c4*4] = make_uint2(bpack(l[0],l[1]), bpack(l[2],l[3]));
        }
        #pragma unroll
        for (int s=0;s<2;s++){
            int idx = t + s*256;
            int r = idx >> 5, c4 = idx & 31;
            __nv_bfloat16 h[4], l[4];
            #pragma unroll
            for (int j=0;j<4;j++){
                h[j] = __float2bfloat16(bval[s][j]);
                l[j] = __float2bfloat16(bval[s][j] - __bfloat162float(h[j]));
            }
            *(uint2*)&Bsh[buf][r*BLD + c4*4] = make_uint2(bpack(h[0],h[1]), bpack(h[2],h[3]));
            *(uint2*)&Bsl[buf][r*BLD + c4*4] = make_uint2(bpack(l[0],l[1]), bpack(l[2],l[3]));
        }
    };

    auto compute = [&](int buf){
        const int arow = wm*64 + (lane & 15);
        const int acol = (lane >> 4)*8;
        uint32_t aAddrH = sptr(&Ash[buf][0]) + (uint32_t)((arow*ALD + acol)*2);
        uint32_t aAddrL = sptr(&Asl[buf][0]) + (uint32_t)((arow*ALD + acol)*2);
        const int brow = lane & 15;
        const int bcol = wn*32 + (lane >> 4)*8;
        uint32_t bAddrH = sptr(&Bsh[buf][0]) + (uint32_t)((brow*BLD + bcol)*2);
        uint32_t bAddrL = sptr(&Bsl[buf][0]) + (uint32_t)((brow*BLD + bcol)*2);

        uint32_t A_[4][4], B[4][2], Bl[4][2];
        #pragma unroll
        for (int mi=0; mi<4; mi++)
            ldsm4(A_[mi][0],A_[mi][1],A_[mi][2],A_[mi][3], aAddrH + (uint32_t)(mi*16*ALD*2));
        #pragma unroll
        for (int np=0; np<2; np++)
            ldsm4t(B[2*np][0],B[2*np][1],B[2*np+1][0],B[2*np+1][1],
                   bAddrH + (uint32_t)(np*16*2));
        #pragma unroll
        for (int np=0; np<2; np++)
            ldsm4t(Bl[2*np][0],Bl[2*np][1],Bl[2*np+1][0],Bl[2*np+1][1],
                   bAddrL + (uint32_t)(np*16*2));
        #pragma unroll
        for (int mi=0; mi<4; mi++)
            #pragma unroll
            for (int ni=0; ni<4; ni++)
                mma16816(acc[mi][ni], A_[mi], B[ni][0], B[ni][1]);
        #pragma unroll
        for (int mi=0; mi<4; mi++)
            #pragma unroll
            for (int ni=0; ni<4; ni++)
                mma16816(acc[mi][ni], A_[mi], Bl[ni][0], Bl[ni][1]);
        #pragma unroll
        for (int mi=0; mi<4; mi++)
            ldsm4(A_[mi][0],A_[mi][1],A_[mi][2],A_[mi][3], aAddrL + (uint32_t)(mi*16*ALD*2));
        #pragma unroll
        for (int mi=0; mi<4; mi++)
            #pragma unroll
            for (int ni=0; ni<4; ni++)
                mma16816(acc[mi][ni], A_[mi], B[ni][0], B[ni][1]);
    };

    const int KS = K/16;
    loadstage(0);
    storestage(0);
    __syncthreads();
    for (int ks=0; ks<KS; ks++){
        if (ks+1 < KS) loadstage(ks+1);
        compute(ks & 1);
        if (ks+1 < KS) storestage((ks+1) & 1);
        __syncthreads();
    }

    const int gid = lane >> 2, tig = lane & 3;
    #pragma unroll
    for (int ni=0; ni<4; ni++){
        int c = col0 + wn*32 + ni*8 + tig*2;
        float2 bb = *(const float2*)(bias + c);
        #pragma unroll
        for (int mi=0; mi<4; mi++){
            int r = row0 + wm*64 + mi*16 + gid;
            if (r < NN){
                float2 o;
                o.x = fmaxf(acc[mi][ni][0] + bb.x, 0.f);
                o.y = fmaxf(acc[mi][ni][1] + bb.y, 0.f);
                *(float2*)(out + (size_t)r*HID + c) = o;
            }
            int r2 = r + 8;
            if (r2 < NN){
                float2 o;
                o.x = fmaxf(acc[mi][ni][2] + bb.x, 0.f);
                o.y = fmaxf(acc[mi][ni][3] + bb.y, 0.f);
                *(float2*)(out + (size_t)r2*HID + c) = o;
            }
        }
    }
}

// ---------------- multipool ----------------
__global__ void pool_kernel(const int* __restrict__ batches){
    const float* h = g_HA;
    __shared__ int idxs[SUBSZ];
    int t = threadIdx.x, b = blockIdx.x;
    if (t < SUBSZ) idxs[t] = batches[b*SUBSZ + t];
    __syncthreads();
    float s = 0.f, mn = 3.4e38f, mx = -3.4e38f;
    #pragma unroll 8
    for (int m = 0; m < SUBSZ; m++){
        float v = h[(size_t)idxs[m]*HID + t];
        s += v; mn = fminf(mn, v); mx = fmaxf(mx, v);
    }
    float* z = g_Z + (size_t)b*4*HID;
    z[t]         = s;
    z[HID + t]   = s * (1.0f/SUBSZ);
    z[2*HID + t] = mn;
    z[3*HID + t] = mx;
}

// ---------------- readout (8 subgraphs per block) + BCE loss ----------------
__global__ void zero_out(float* out){
    if (threadIdx.x == 0 && blockIdx.x == 0) out[0] = 0.f;
}

__global__ __launch_bounds__(256)
void readout8(const float* __restrict__ Wr1, const float* __restrict__ br1,
              const float* __restrict__ Wr2, const float* __restrict__ br2,
              const float* __restrict__ labels, float* out){
    const int b0 = blockIdx.x*8;
    __shared__ float z[8*4*HID];
    int t = threadIdx.x;
    const float4* zg = (const float4*)(g_Z + (size_t)b0*4*HID);
    #pragma unroll
    for (int j = t; j < 8*4*HID/4; j += 256)
        ((float4*)z)[j] = zg[j];
    __syncthreads();

    float bb = br1[t];
    float acc[8];
    #pragma unroll
    for (int j=0;j<8;j++) acc[j] = bb;

    #pragma unroll 8
    for (int k=0;k<4*HID;k++){
        float w = Wr1[(size_t)k*HID + t];
        #pragma unroll
        for (int j=0;j<8;j++) acc[j] += z[j*4*HID + k]*w;
    }
    __syncthreads();
    float wr2 = Wr2[t];
    #pragma unroll
    for (int j=0;j<8;j++) z[j*HID + t] = fmaxf(acc[j], 0.f)*wr2;
    __syncthreads();

    int w = t >> 5, lane = t & 31;
    float s = 0.f;
    #pragma unroll
    for (int q=0;q<8;q++) s += z[w*HID + lane + q*32];
    #pragma unroll
    for (int off=16; off>0; off>>=1) s += __shfl_xor_sync(0xffffffffu, s, off);
    if (lane == 0){
        float p = s + br2[0];
        float l = labels[b0 + w];
        float term = fmaxf(p, 0.f) - p*l + log1pf(expf(-fabsf(p)));
        atomicAdd(out, term * (1.0f/NSUB));
    }
}

// ---------------- launch ----------------
extern "C" void kernel_launch(void* const* d_in, const int* in_sizes, int n_in,
                              void* d_out, int out_size){
    const float* x       = (const float*)d_in[0];
    const int*   esrc    = (const int*)  d_in[1];
    const int*   edst    = (const int*)  d_in[2];
    const float* ew      = (const float*)d_in[3];
    const int*   batches = (const int*)  d_in[4];
    const float* labels  = (const float*)d_in[6];
    const float* W0      = (const float*)d_in[7];
    const float* b0      = (const float*)d_in[8];
    const float* W1      = (const float*)d_in[9];
    const float* b1      = (const float*)d_in[10];
    const float* W2      = (const float*)d_in[11];
    const float* b2      = (const float*)d_in[12];
    const float* eps     = (const float*)d_in[13];
    const float* Wr1     = (const float*)d_in[14];
    const float* br1     = (const float*)d_in[15];
    const float* Wr2     = (const float*)d_in[16];
    const float* br2     = (const float*)d_in[17];
    float* out = (float*)d_out;

    // input prep
    build_h0<<<4096, 256>>>(x);
    scatter_batch<<<(MTOT+255)/256, 256>>>(batches);
    build_w0p<<<(K0*HID+255)/256, 256>>>(W0);

    // CSR build (by dst)
    zero_degcur<<<(NN+255)/256, 256>>>();
    hist_dst<<<(NE+255)/256, 256>>>(edst);
    scan_block<<<NBLK, SCAN_B>>>();
    scan_bsums<<<1, 256>>>();
    scan_add<<<NBLK, SCAN_B>>>();
    csr_scatter<<<(NE+255)/256, 256>>>(esrc, edst, ew);

    dim3 gemmGrid(2, (NN+127)/128);
    const int gatherGrid = (NN+7)/8;

    // layer 0: K=160 (cols 0..131 live, rest zero)
    csr_gather<<<gatherGrid, 256>>>(0, eps, 0, K0, 33, 40);
    gemm_mma<K0><<<gemmGrid, 256>>>(nullptr, 4, b0, 2);

    // layer 1
    csr_gather<<<gatherGrid, 256>>>(2, eps, 1, HID, 64, 64);
    gemm_mma<HID><<<gemmGrid, 256>>>(W1, -1, b1, 3);

    // layer 2
    csr_gather<<<gatherGrid, 256>>>(3, eps, 2, HID, 64, 64);
    gemm_mma<HID><<<gemmGrid, 256>>>(W2, -1, b2, 2);

    pool_kernel<<<NSUB, HID>>>(batches);
    zero_out<<<1, 32>>>(out);
    readout8<<<NSUB/8, 256>>>(Wr1, br1, Wr2, br2, labels, out);
}

// round 5
// speedup vs baseline: 2.2334x; 1.0603x over previous
#include <cuda_runtime.h>
#include <cuda_bf16.h>
#include <math.h>
#include <stdint.h>

#define NN    50000
#define FEAT  128
#define HID   256
#define K0    160        // layer-0 K (129 live -> 132 used) padded to 160
#define NE    800000
#define NSUB  512
#define SUBSZ 64
#define MTOT  (NSUB*SUBSZ)

#define SCAN_B 256
#define NBLK   ((NN + SCAN_B - 1) / SCAN_B)   // 196

// ---------------- scratch (device globals; no allocation allowed) ----------------
__device__ __align__(16) float          g_MSG[NN*HID];   // f32 GEMM A (160-col view for L0)
__device__ __align__(16) __nv_bfloat16  g_B0 [NN*K0];    // bf16 h0
__device__ __align__(16) __nv_bfloat16  g_BA [NN*HID];   // bf16 h (layers)
__device__ __align__(16) __nv_bfloat16  g_BB [NN*HID];
__device__ __align__(16) float          g_W0p[K0*HID];   // zero-padded W0
__device__ __align__(16) float          g_Z  [NSUB*4*HID];
// CSR scratch
__device__ int   g_deg [NN];
__device__ int   g_cur [NN];
__device__ int   g_off [NN+1];
__device__ int   g_bsum[NBLK];
__device__ int   g_csrc[NE];
__device__ float g_cw  [NE];

__device__ __forceinline__ __nv_bfloat16* gbuf16(int id){
    switch(id){
        case 0: return g_B0;
        case 1: return g_BA;
        default: return g_BB;
    }
}

// ---------------- setup ----------------
__global__ void build_h0(const float* __restrict__ x){
    int idx = blockIdx.x*blockDim.x + threadIdx.x;
    const int total = NN*K0;
    for (; idx < total; idx += gridDim.x*blockDim.x){
        int i = idx / K0;
        int c = idx - i*K0;
        g_B0[idx] = (c < FEAT) ? __float2bfloat16(x[i*FEAT + c]) : __float2bfloat16(0.f);
    }
}

__global__ void scatter_batch(const int* __restrict__ batches){
    int m = blockIdx.x*blockDim.x + threadIdx.x;
    if (m < MTOT) g_B0[(size_t)batches[m]*K0 + FEAT] = __float2bfloat16(1.0f);
}

__global__ void build_w0p(const float* __restrict__ W0){
    int idx = blockIdx.x*blockDim.x + threadIdx.x;
    if (idx < K0*HID){
        int r = idx / HID;
        int c = idx - r*HID;
        g_W0p[idx] = (r < FEAT+1) ? W0[r*HID + c] : 0.0f;
    }
}

// ---------------- CSR build ----------------
__global__ void zero_degcur(){
    int i = blockIdx.x*blockDim.x + threadIdx.x;
    if (i < NN){ g_deg[i] = 0; g_cur[i] = 0; }
}

__global__ void hist_dst(const int* __restrict__ dst){
    int e = blockIdx.x*blockDim.x + threadIdx.x;
    if (e < NE) atomicAdd(&g_deg[dst[e]], 1);
}

__global__ void scan_block(){
    __shared__ int sh[SCAN_B];
    int i = blockIdx.x*SCAN_B + threadIdx.x;
    int v = (i < NN) ? g_deg[i] : 0;
    sh[threadIdx.x] = v;
    __syncthreads();
    #pragma unroll
    for (int off = 1; off < SCAN_B; off <<= 1){
        int add = (threadIdx.x >= off) ? sh[threadIdx.x - off] : 0;
        __syncthreads();
        sh[threadIdx.x] += add;
        __syncthreads();
    }
    if (i < NN) g_off[i] = sh[threadIdx.x] - v;
    if (threadIdx.x == SCAN_B-1) g_bsum[blockIdx.x] = sh[SCAN_B-1];
}

__global__ void scan_bsums(){
    __shared__ int sh[256];
    int t = threadIdx.x;
    int v = (t < NBLK) ? g_bsum[t] : 0;
    sh[t] = v;
    __syncthreads();
    #pragma unroll
    for (int off = 1; off < 256; off <<= 1){
        int add = (t >= off) ? sh[t - off] : 0;
        __syncthreads();
        sh[t] += add;
        __syncthreads();
    }
    if (t < NBLK) g_bsum[t] = sh[t] - v;
}

__global__ void scan_add(){
    int i = blockIdx.x*SCAN_B + threadIdx.x;
    if (i < NN) g_off[i] += g_bsum[blockIdx.x];
    if (i == 0) g_off[NN] = NE;
}

__global__ void csr_scatter(const int* __restrict__ src, const int* __restrict__ dst,
                            const float* __restrict__ ew){
    int e = blockIdx.x*blockDim.x + threadIdx.x;
    if (e < NE){
        int d = dst[e];
        int pos = g_off[d] + atomicAdd(&g_cur[d], 1);
        g_csrc[pos] = src[e];
        g_cw[pos]   = ew[e];
    }
}

// ---------------- gather (bf16 inputs, f32 accumulate) ----------------
// MSG[n] = (1+eps)*h[n] + sum_{e: dst=n} w_e * h[src_e]
__global__ __launch_bounds__(256)
void csr_gather(int hsel, const float* __restrict__ eps, int ei, int ld, int w4r, int w4p){
    const __nv_bfloat16* h = gbuf16(hsel);
    int n = blockIdx.x*8 + (threadIdx.x >> 5);
    if (n >= NN) return;
    int lane = threadIdx.x & 31;
    int s0 = g_off[n], s1 = g_off[n+1];

    const bool a0 = (lane      < w4r);
    const bool a1 = (lane + 32 < w4r);
    float4 acc0 = make_float4(0.f,0.f,0.f,0.f);
    float4 acc1 = make_float4(0.f,0.f,0.f,0.f);

    int   s_nxt = 0;
    float w_nxt = 0.f;
    if (s0 < s1){
        s_nxt = __ldg(&g_csrc[s0]);
        w_nxt = __ldg(&g_cw[s0]);
    }
    for (int e = s0; e < s1; e++){
        int   s = s_nxt;
        float w = w_nxt;
        if (e+1 < s1){
            s_nxt = __ldg(&g_csrc[e+1]);
            w_nxt = __ldg(&g_cw[e+1]);
        }
        const uint2* hs = (const uint2*)(h + (size_t)s*ld);
        if (a0){
            uint2 u = __ldg(&hs[lane]);
            float2 f0 = __bfloat1622float2(*(__nv_bfloat162*)&u.x);
            float2 f1 = __bfloat1622float2(*(__nv_bfloat162*)&u.y);
            acc0.x += w*f0.x; acc0.y += w*f0.y; acc0.z += w*f1.x; acc0.w += w*f1.y;
        }
        if (a1){
            uint2 u = __ldg(&hs[lane+32]);
            float2 f0 = __bfloat1622float2(*(__nv_bfloat162*)&u.x);
            float2 f1 = __bfloat1622float2(*(__nv_bfloat162*)&u.y);
            acc1.x += w*f0.x; acc1.y += w*f0.y; acc1.z += w*f1.x; acc1.w += w*f1.y;
        }
    }

    const float ep = 1.0f + eps[ei];
    const uint2* hn = (const uint2*)(h + (size_t)n*ld);
    float4* mrow = (float4*)(g_MSG + (size_t)n*ld);
    if (a0){
        uint2 u = __ldg(&hn[lane]);
        float2 f0 = __bfloat1622float2(*(__nv_bfloat162*)&u.x);
        float2 f1 = __bfloat1622float2(*(__nv_bfloat162*)&u.y);
        acc0.x += ep*f0.x; acc0.y += ep*f0.y; acc0.z += ep*f1.x; acc0.w += ep*f1.y;
        mrow[lane] = acc0;
    }
    if (a1){
        uint2 u = __ldg(&hn[lane+32]);
        float2 f0 = __bfloat1622float2(*(__nv_bfloat162*)&u.x);
        float2 f1 = __bfloat1622float2(*(__nv_bfloat162*)&u.y);
        acc1.x += ep*f0.x; acc1.y += ep*f0.y; acc1.z += ep*f1.x; acc1.w += ep*f1.y;
        mrow[lane+32] = acc1;
    } else if (lane + 32 < w4p){
        mrow[lane+32] = make_float4(0.f,0.f,0.f,0.f);
    }
}

// ---------------- tensor-core GIN GEMM: outb16 = relu(MSG @ W + b) ------
__device__ __forceinline__ uint32_t sptr(const void* p){
    return (uint32_t)__cvta_generic_to_shared(p);
}
__device__ __forceinline__ void ldsm4(uint32_t& r0,uint32_t& r1,uint32_t& r2,uint32_t& r3, uint32_t a){
    asm volatile("ldmatrix.sync.aligned.m8n8.x4.shared.b16 {%0,%1,%2,%3},[%4];"
                 : "=r"(r0),"=r"(r1),"=r"(r2),"=r"(r3) : "r"(a));
}
__device__ __forceinline__ void ldsm4t(uint32_t& r0,uint32_t& r1,uint32_t& r2,uint32_t& r3, uint32_t a){
    asm volatile("ldmatrix.sync.aligned.m8n8.x4.trans.shared.b16 {%0,%1,%2,%3},[%4];"
                 : "=r"(r0),"=r"(r1),"=r"(r2),"=r"(r3) : "r"(a));
}
__device__ __forceinline__ void mma16816(float* c, const uint32_t* a, uint32_t b0, uint32_t b1){
    asm volatile("mma.sync.aligned.m16n8k16.row.col.f32.bf16.bf16.f32 "
                 "{%0,%1,%2,%3},{%4,%5,%6,%7},{%8,%9},{%0,%1,%2,%3};"
                 : "+f"(c[0]),"+f"(c[1]),"+f"(c[2]),"+f"(c[3])
                 : "r"(a[0]),"r"(a[1]),"r"(a[2]),"r"(a[3]),"r"(b0),"r"(b1));
}
__device__ __forceinline__ uint32_t bpack(__nv_bfloat16 a, __nv_bfloat16 b){
    __nv_bfloat162 t = __halves2bfloat162(a,b);
    return *reinterpret_cast<uint32_t*>(&t);
}

#define ALD 24
#define BLD 136

template<int K>
__global__ __launch_bounds__(256)
void gemm_mma(const float* __restrict__ Wp, int useW0p,
              const float* __restrict__ bias, int osel){
    const float* A = g_MSG;
    const float* W = useW0p ? g_W0p : Wp;
    __nv_bfloat16* out = gbuf16(osel);

    __shared__ __nv_bfloat16 Ash[2][128*ALD];
    __shared__ __nv_bfloat16 Asl[2][128*ALD];
    __shared__ __nv_bfloat16 Bsh[2][16*BLD];
    __shared__ __nv_bfloat16 Bsl[2][16*BLD];

    const int t = threadIdx.x;
    const int warp = t >> 5, lane = t & 31;
    const int wm = warp >> 2, wn = warp & 3;
    const int row0 = blockIdx.y*128, col0 = blockIdx.x*128;

    float acc[4][4][4];
    #pragma unroll
    for (int i=0;i<4;i++)
        #pragma unroll
        for (int j=0;j<4;j++)
            #pragma unroll
            for (int q=0;q<4;q++) acc[i][j][q]=0.f;

    float aval[2][4];
    float bval[2][4];

    auto loadstage = [&](int ks){
        const int k0 = ks*16;
        #pragma unroll
        for (int s=0;s<2;s++){
            int idx = t + s*256;
            int r = idx >> 2, c4 = idx & 3;
            int gr = row0 + r;
            float4 mv = make_float4(0.f,0.f,0.f,0.f);
            if (gr < NN)
                mv = *(const float4*)(A + (size_t)gr*K + k0 + c4*4);
            aval[s][0]=mv.x; aval[s][1]=mv.y; aval[s][2]=mv.z; aval[s][3]=mv.w;
        }
        #pragma unroll
        for (int s=0;s<2;s++){
            int idx = t + s*256;
            int r = idx >> 5, c4 = idx & 31;
            float4 wv = *(const float4*)(W + (size_t)(k0 + r)*HID + col0 + c4*4);
            bval[s][0]=wv.x; bval[s][1]=wv.y; bval[s][2]=wv.z; bval[s][3]=wv.w;
        }
    };

    auto storestage = [&](int buf){
        #pragma unroll
        for (int s=0;s<2;s++){
            int idx = t + s*256;
            int r = idx >> 2, c4 = idx & 3;
            __nv_bfloat16 h[4], l[4];
            #pragma unroll
            for (int j=0;j<4;j++){
                h[j] = __float2bfloat16(aval[s][j]);
                l[j] = __float2bfloat16(aval[s][j] - __bfloat162float(h[j]));
            }
            *(uint2*)&Ash[buf][r*ALD + c4*4] = make_uint2(bpack(h[0],h[1]), bpack(h[2],h[3]));
            *(uint2*)&Asl[buf][r*ALD + c4*4] = make_uint2(bpack(l[0],l[1]), bpack(l[2],l[3]));
        }
        #pragma unroll
        for (int s=0;s<2;s++){
            int idx = t + s*256;
            int r = idx >> 5, c4 = idx & 31;
            __nv_bfloat16 h[4], l[4];
            #pragma unroll
            for (int j=0;j<4;j++){
                h[j] = __float2bfloat16(bval[s][j]);
                l[j] = __float2bfloat16(bval[s][j] - __bfloat162float(h[j]));
            }
            *(uint2*)&Bsh[buf][r*BLD + c4*4] = make_uint2(bpack(h[0],h[1]), bpack(h[2],h[3]));
            *(uint2*)&Bsl[buf][r*BLD + c4*4] = make_uint2(bpack(l[0],l[1]), bpack(l[2],l[3]));
        }
    };

    auto compute = [&](int buf){
        const int arow = wm*64 + (lane & 15);
        const int acol = (lane >> 4)*8;
        uint32_t aAddrH = sptr(&Ash[buf][0]) + (uint32_t)((arow*ALD + acol)*2);
        uint32_t aAddrL = sptr(&Asl[buf][0]) + (uint32_t)((arow*ALD + acol)*2);
        const int brow = lane & 15;
        const int bcol = wn*32 + (lane >> 4)*8;
        uint32_t bAddrH = sptr(&Bsh[buf][0]) + (uint32_t)((brow*BLD + bcol)*2);
        uint32_t bAddrL = sptr(&Bsl[buf][0]) + (uint32_t)((brow*BLD + bcol)*2);

        uint32_t A_[4][4], B[4][2], Bl[4][2];
        #pragma unroll
        for (int mi=0; mi<4; mi++)
            ldsm4(A_[mi][0],A_[mi][1],A_[mi][2],A_[mi][3], aAddrH + (uint32_t)(mi*16*ALD*2));
        #pragma unroll
        for (int np=0; np<2; np++)
            ldsm4t(B[2*np][0],B[2*np][1],B[2*np+1][0],B[2*np+1][1],
                   bAddrH + (uint32_t)(np*16*2));
        #pragma unroll
        for (int np=0; np<2; np++)
            ldsm4t(Bl[2*np][0],Bl[2*np][1],Bl[2*np+1][0],Bl[2*np+1][1],
                   bAddrL + (uint32_t)(np*16*2));
        #pragma unroll
        for (int mi=0; mi<4; mi++)
            #pragma unroll
            for (int ni=0; ni<4; ni++)
                mma16816(acc[mi][ni], A_[mi], B[ni][0], B[ni][1]);
        #pragma unroll
        for (int mi=0; mi<4; mi++)
            #pragma unroll
            for (int ni=0; ni<4; ni++)
                mma16816(acc[mi][ni], A_[mi], Bl[ni][0], Bl[ni][1]);
        #pragma unroll
        for (int mi=0; mi<4; mi++)
            ldsm4(A_[mi][0],A_[mi][1],A_[mi][2],A_[mi][3], aAddrL + (uint32_t)(mi*16*ALD*2));
        #pragma unroll
        for (int mi=0; mi<4; mi++)
            #pragma unroll
            for (int ni=0; ni<4; ni++)
                mma16816(acc[mi][ni], A_[mi], B[ni][0], B[ni][1]);
    };

    const int KS = K/16;
    loadstage(0);
    storestage(0);
    __syncthreads();
    for (int ks=0; ks<KS; ks++){
        if (ks+1 < KS) loadstage(ks+1);
        compute(ks & 1);
        if (ks+1 < KS) storestage((ks+1) & 1);
        __syncthreads();
    }

    // epilogue: bias + relu, bf16 stores
    const int gid = lane >> 2, tig = lane & 3;
    #pragma unroll
    for (int ni=0; ni<4; ni++){
        int c = col0 + wn*32 + ni*8 + tig*2;
        float2 bb = *(const float2*)(bias + c);
        #pragma unroll
        for (int mi=0; mi<4; mi++){
            int r = row0 + wm*64 + mi*16 + gid;
            if (r < NN){
                __nv_bfloat162 o = __floats2bfloat162_rn(
                    fmaxf(acc[mi][ni][0] + bb.x, 0.f),
                    fmaxf(acc[mi][ni][1] + bb.y, 0.f));
                *(__nv_bfloat162*)(out + (size_t)r*HID + c) = o;
            }
            int r2 = r + 8;
            if (r2 < NN){
                __nv_bfloat162 o = __floats2bfloat162_rn(
                    fmaxf(acc[mi][ni][2] + bb.x, 0.f),
                    fmaxf(acc[mi][ni][3] + bb.y, 0.f));
                *(__nv_bfloat162*)(out + (size_t)r2*HID + c) = o;
            }
        }
    }
}

// ---------------- multipool (bf16 input) ----------------
__global__ void pool_kernel(const int* __restrict__ batches){
    const __nv_bfloat16* h = g_BA;   // final layer output
    __shared__ int idxs[SUBSZ];
    int t = threadIdx.x, b = blockIdx.x;
    if (t < SUBSZ) idxs[t] = batches[b*SUBSZ + t];
    __syncthreads();
    float s = 0.f, mn = 3.4e38f, mx = -3.4e38f;
    #pragma unroll 8
    for (int m = 0; m < SUBSZ; m++){
        float v = __bfloat162float(h[(size_t)idxs[m]*HID + t]);
        s += v; mn = fminf(mn, v); mx = fmaxf(mx, v);
    }
    float* z = g_Z + (size_t)b*4*HID;
    z[t]         = s;
    z[HID + t]   = s * (1.0f/SUBSZ);
    z[2*HID + t] = mn;
    z[3*HID + t] = mx;
}

// ---------------- readout + BCE ----------------
__global__ void zero_out(float* out){
    if (threadIdx.x == 0 && blockIdx.x == 0) out[0] = 0.f;
}

__global__ __launch_bounds__(256)
void readout8(const float* __restrict__ Wr1, const float* __restrict__ br1,
              const float* __restrict__ Wr2, const float* __restrict__ br2,
              const float* __restrict__ labels, float* out){
    const int b0 = blockIdx.x*8;
    __shared__ float z[8*4*HID];
    int t = threadIdx.x;
    const float4* zg = (const float4*)(g_Z + (size_t)b0*4*HID);
    #pragma unroll
    for (int j = t; j < 8*4*HID/4; j += 256)
        ((float4*)z)[j] = zg[j];
    __syncthreads();

    float bb = br1[t];
    float acc[8];
    #pragma unroll
    for (int j=0;j<8;j++) acc[j] = bb;

    #pragma unroll 8
    for (int k=0;k<4*HID;k++){
        float w = Wr1[(size_t)k*HID + t];
        #pragma unroll
        for (int j=0;j<8;j++) acc[j] += z[j*4*HID + k]*w;
    }
    __syncthreads();
    float wr2 = Wr2[t];
    #pragma unroll
    for (int j=0;j<8;j++) z[j*HID + t] = fmaxf(acc[j], 0.f)*wr2;
    __syncthreads();

    int w = t >> 5, lane = t & 31;
    float s = 0.f;
    #pragma unroll
    for (int q=0;q<8;q++) s += z[w*HID + lane + q*32];
    #pragma unroll
    for (int off=16; off>0; off>>=1) s += __shfl_xor_sync(0xffffffffu, s, off);
    if (lane == 0){
        float p = s + br2[0];
        float l = labels[b0 + w];
        float term = fmaxf(p, 0.f) - p*l + log1pf(expf(-fabsf(p)));
        atomicAdd(out, term * (1.0f/NSUB));
    }
}

// ---------------- launch ----------------
extern "C" void kernel_launch(void* const* d_in, const int* in_sizes, int n_in,
                              void* d_out, int out_size){
    const float* x       = (const float*)d_in[0];
    const int*   esrc    = (const int*)  d_in[1];
    const int*   edst    = (const int*)  d_in[2];
    const float* ew      = (const float*)d_in[3];
    const int*   batches = (const int*)  d_in[4];
    const float* labels  = (const float*)d_in[6];
    const float* W0      = (const float*)d_in[7];
    const float* b0      = (const float*)d_in[8];
    const float* W1      = (const float*)d_in[9];
    const float* b1      = (const float*)d_in[10];
    const float* W2      = (const float*)d_in[11];
    const float* b2      = (const float*)d_in[12];
    const float* eps     = (const float*)d_in[13];
    const float* Wr1     = (const float*)d_in[14];
    const float* br1     = (const float*)d_in[15];
    const float* Wr2     = (const float*)d_in[16];
    const float* br2     = (const float*)d_in[17];
    float* out = (float*)d_out;

    // prep
    build_h0<<<4096, 256>>>(x);
    scatter_batch<<<(MTOT+255)/256, 256>>>(batches);
    build_w0p<<<(K0*HID+255)/256, 256>>>(W0);

    // CSR build (by dst)
    zero_degcur<<<(NN+255)/256, 256>>>();
    hist_dst<<<(NE+255)/256, 256>>>(edst);
    scan_block<<<NBLK, SCAN_B>>>();
    scan_bsums<<<1, 256>>>();
    scan_add<<<NBLK, SCAN_B>>>();
    csr_scatter<<<(NE+255)/256, 256>>>(esrc, edst, ew);

    dim3 gemmGrid(2, (NN+127)/128);
    const int gatherGrid = (NN+7)/8;

    // layer 0: 132 live cols (33 units), pad to 160 (40 units)
    csr_gather<<<gatherGrid, 256>>>(0, eps, 0, K0, 33, 40);
    gemm_mma<K0><<<gemmGrid, 256>>>(nullptr, 1, b0, 1);

    // layer 1
    csr_gather<<<gatherGrid, 256>>>(1, eps, 1, HID, 64, 64);
    gemm_mma<HID><<<gemmGrid, 256>>>(W1, 0, b1, 2);

    // layer 2
    csr_gather<<<gatherGrid, 256>>>(2, eps, 2, HID, 64, 64);
    gemm_mma<HID><<<gemmGrid, 256>>>(W2, 0, b2, 1);

    pool_kernel<<<NSUB, HID>>>(batches);
    zero_out<<<1, 32>>>(out);
    readout8<<<NSUB/8, 256>>>(Wr1, br1, Wr2, br2, labels, out);
}

// round 6
// speedup vs baseline: 2.2485x; 1.0068x over previous
#include <cuda_runtime.h>
#include <cuda_bf16.h>
#include <math.h>
#include <stdint.h>

#define NN    50000
#define FEAT  128
#define HID   256
#define K0    160        // layer-0 K (129 live -> 132 used) padded to 160
#define NE    800000
#define NSUB  512
#define SUBSZ 64
#define MTOT  (NSUB*SUBSZ)

#define SCAN_B 256
#define NBLK   ((NN + SCAN_B - 1) / SCAN_B)   // 196

// ---------------- scratch (device globals; no allocation allowed) ----------------
__device__ __align__(16) float          g_MSG[NN*HID];   // f32 GEMM A (160-col view for L0)
__device__ __align__(16) __nv_bfloat16  g_B0 [NN*K0];    // bf16 h0
__device__ __align__(16) __nv_bfloat16  g_BA [NN*HID];   // bf16 h (layers)
__device__ __align__(16) __nv_bfloat16  g_BB [NN*HID];
__device__ __align__(16) float          g_W0p[K0*HID];   // zero-padded W0
__device__ __align__(16) float          g_Z  [NSUB*4*HID];
// CSR scratch
__device__ int   g_deg [NN];
__device__ int   g_cur [NN];
__device__ int   g_off [NN+1];
__device__ int   g_bsum[NBLK];
__device__ int   g_csrc[NE];
__device__ float g_cw  [NE];

__device__ __forceinline__ __nv_bfloat16* gbuf16(int id){
    switch(id){
        case 0: return g_B0;
        case 1: return g_BA;
        default: return g_BB;
    }
}

// ---------------- setup ----------------
__global__ void build_h0(const float* __restrict__ x){
    int idx = blockIdx.x*blockDim.x + threadIdx.x;
    const int total = NN*K0;
    for (; idx < total; idx += gridDim.x*blockDim.x){
        int i = idx / K0;
        int c = idx - i*K0;
        g_B0[idx] = (c < FEAT) ? __float2bfloat16(x[i*FEAT + c]) : __float2bfloat16(0.f);
    }
}

__global__ void scatter_batch(const int* __restrict__ batches){
    int m = blockIdx.x*blockDim.x + threadIdx.x;
    if (m < MTOT) g_B0[(size_t)batches[m]*K0 + FEAT] = __float2bfloat16(1.0f);
}

__global__ void build_w0p(const float* __restrict__ W0){
    int idx = blockIdx.x*blockDim.x + threadIdx.x;
    if (idx < K0*HID){
        int r = idx / HID;
        int c = idx - r*HID;
        g_W0p[idx] = (r < FEAT+1) ? W0[r*HID + c] : 0.0f;
    }
}

// ---------------- CSR build ----------------
__global__ void zero_degcur(){
    int i = blockIdx.x*blockDim.x + threadIdx.x;
    if (i < NN){ g_deg[i] = 0; g_cur[i] = 0; }
}

__global__ void hist_dst(const int* __restrict__ dst){
    int e = blockIdx.x*blockDim.x + threadIdx.x;
    if (e < NE) atomicAdd(&g_deg[dst[e]], 1);
}

__global__ void scan_block(){
    __shared__ int sh[SCAN_B];
    int i = blockIdx.x*SCAN_B + threadIdx.x;
    int v = (i < NN) ? g_deg[i] : 0;
    sh[threadIdx.x] = v;
    __syncthreads();
    #pragma unroll
    for (int off = 1; off < SCAN_B; off <<= 1){
        int add = (threadIdx.x >= off) ? sh[threadIdx.x - off] : 0;
        __syncthreads();
        sh[threadIdx.x] += add;
        __syncthreads();
    }
    if (i < NN) g_off[i] = sh[threadIdx.x] - v;
    if (threadIdx.x == SCAN_B-1) g_bsum[blockIdx.x] = sh[SCAN_B-1];
}

__global__ void scan_bsums(){
    __shared__ int sh[256];
    int t = threadIdx.x;
    int v = (t < NBLK) ? g_bsum[t] : 0;
    sh[t] = v;
    __syncthreads();
    #pragma unroll
    for (int off = 1; off < 256; off <<= 1){
        int add = (t >= off) ? sh[t - off] : 0;
        __syncthreads();
        sh[t] += add;
        __syncthreads();
    }
    if (t < NBLK) g_bsum[t] = sh[t] - v;
}

__global__ void scan_add(){
    int i = blockIdx.x*SCAN_B + threadIdx.x;
    if (i < NN) g_off[i] += g_bsum[blockIdx.x];
    if (i == 0) g_off[NN] = NE;
}

__global__ void csr_scatter(const int* __restrict__ src, const int* __restrict__ dst,
                            const float* __restrict__ ew){
    int e = blockIdx.x*blockDim.x + threadIdx.x;
    if (e < NE){
        int d = dst[e];
        int pos = g_off[d] + atomicAdd(&g_cur[d], 1);
        g_csrc[pos] = src[e];
        g_cw[pos]   = ew[e];
    }
}

// ---------------- gather (bf16 inputs, f32 accumulate, edge-unroll x4) ----------------
// MSG[n] = (1+eps)*h[n] + sum_{e: dst=n} w_e * h[src_e]
__device__ __forceinline__ void facc(float4& a, float w, uint2 u){
    float2 f0 = __bfloat1622float2(*(__nv_bfloat162*)&u.x);
    float2 f1 = __bfloat1622float2(*(__nv_bfloat162*)&u.y);
    a.x += w*f0.x; a.y += w*f0.y; a.z += w*f1.x; a.w += w*f1.y;
}

__global__ __launch_bounds__(256)
void csr_gather(int hsel, const float* __restrict__ eps, int ei, int ld, int w4r, int w4p){
    const __nv_bfloat16* h = gbuf16(hsel);
    int n = blockIdx.x*8 + (threadIdx.x >> 5);
    if (n >= NN) return;
    int lane = threadIdx.x & 31;
    int s0 = g_off[n], s1 = g_off[n+1];

    const bool a0 = (lane      < w4r);
    const bool a1 = (lane + 32 < w4r);
    float4 acc0 = make_float4(0.f,0.f,0.f,0.f);
    float4 acc1 = make_float4(0.f,0.f,0.f,0.f);

    int e = s0;
    // unrolled by 4: all 8 row loads per lane in flight before consumption
    for (; e + 4 <= s1; e += 4){
        int   si[4]; float wi[4];
        #pragma unroll
        for (int j=0;j<4;j++){
            si[j] = __ldg(&g_csrc[e+j]);
            wi[j] = __ldg(&g_cw[e+j]);
        }
        uint2 u0[4], u1[4];
        #pragma unroll
        for (int j=0;j<4;j++){
            const uint2* hs = (const uint2*)(h + (size_t)si[j]*ld);
            if (a0) u0[j] = __ldg(&hs[lane]);
            if (a1) u1[j] = __ldg(&hs[lane+32]);
        }
        #pragma unroll
        for (int j=0;j<4;j++){
            if (a0) facc(acc0, wi[j], u0[j]);
            if (a1) facc(acc1, wi[j], u1[j]);
        }
    }
    // remainder
    for (; e < s1; e++){
        int   s = __ldg(&g_csrc[e]);
        float w = __ldg(&g_cw[e]);
        const uint2* hs = (const uint2*)(h + (size_t)s*ld);
        if (a0){ uint2 u = __ldg(&hs[lane]);    facc(acc0, w, u); }
        if (a1){ uint2 u = __ldg(&hs[lane+32]); facc(acc1, w, u); }
    }

    const float ep = 1.0f + eps[ei];
    const uint2* hn = (const uint2*)(h + (size_t)n*ld);
    float4* mrow = (float4*)(g_MSG + (size_t)n*ld);
    if (a0){
        uint2 u = __ldg(&hn[lane]);
        facc(acc0, ep, u);
        mrow[lane] = acc0;
    }
    if (a1){
        uint2 u = __ldg(&hn[lane+32]);
        facc(acc1, ep, u);
        mrow[lane+32] = acc1;
    } else if (lane + 32 < w4p){
        mrow[lane+32] = make_float4(0.f,0.f,0.f,0.f);
    }
}

// ---------------- tensor-core GIN GEMM: outb16 = relu(MSG @ W + b) ------
__device__ __forceinline__ uint32_t sptr(const void* p){
    return (uint32_t)__cvta_generic_to_shared(p);
}
__device__ __forceinline__ void ldsm4(uint32_t& r0,uint32_t& r1,uint32_t& r2,uint32_t& r3, uint32_t a){
    asm volatile("ldmatrix.sync.aligned.m8n8.x4.shared.b16 {%0,%1,%2,%3},[%4];"
                 : "=r"(r0),"=r"(r1),"=r"(r2),"=r"(r3) : "r"(a));
}
__device__ __forceinline__ void ldsm4t(uint32_t& r0,uint32_t& r1,uint32_t& r2,uint32_t& r3, uint32_t a){
    asm volatile("ldmatrix.sync.aligned.m8n8.x4.trans.shared.b16 {%0,%1,%2,%3},[%4];"
                 : "=r"(r0),"=r"(r1),"=r"(r2),"=r"(r3) : "r"(a));
}
__device__ __forceinline__ void mma16816(float* c, const uint32_t* a, uint32_t b0, uint32_t b1){
    asm volatile("mma.sync.aligned.m16n8k16.row.col.f32.bf16.bf16.f32 "
                 "{%0,%1,%2,%3},{%4,%5,%6,%7},{%8,%9},{%0,%1,%2,%3};"
                 : "+f"(c[0]),"+f"(c[1]),"+f"(c[2]),"+f"(c[3])
                 : "r"(a[0]),"r"(a[1]),"r"(a[2]),"r"(a[3]),"r"(b0),"r"(b1));
}
__device__ __forceinline__ uint32_t bpack(__nv_bfloat16 a, __nv_bfloat16 b){
    __nv_bfloat162 t = __halves2bfloat162(a,b);
    return *reinterpret_cast<uint32_t*>(&t);
}

#define ALD 24
#define BLD 136

template<int K>
__global__ __launch_bounds__(256)
void gemm_mma(const float* __restrict__ Wp, int useW0p,
              const float* __restrict__ bias, int osel){
    const float* A = g_MSG;
    const float* W = useW0p ? g_W0p : Wp;
    __nv_bfloat16* out = gbuf16(osel);

    __shared__ __nv_bfloat16 Ash[2][128*ALD];
    __shared__ __nv_bfloat16 Asl[2][128*ALD];
    __shared__ __nv_bfloat16 Bsh[2][16*BLD];
    __shared__ __nv_bfloat16 Bsl[2][16*BLD];

    const int t = threadIdx.x;
    const int warp = t >> 5, lane = t & 31;
    const int wm = warp >> 2, wn = warp & 3;
    const int row0 = blockIdx.y*128, col0 = blockIdx.x*128;

    float acc[4][4][4];
    #pragma unroll
    for (int i=0;i<4;i++)
        #pragma unroll
        for (int j=0;j<4;j++)
            #pragma unroll
            for (int q=0;q<4;q++) acc[i][j][q]=0.f;

    float aval[2][4];
    float bval[2][4];

    auto loadstage = [&](int ks){
        const int k0 = ks*16;
        #pragma unroll
        for (int s=0;s<2;s++){
            int idx = t + s*256;
            int r = idx >> 2, c4 = idx & 3;
            int gr = row0 + r;
            float4 mv = make_float4(0.f,0.f,0.f,0.f);
            if (gr < NN)
                mv = *(const float4*)(A + (size_t)gr*K + k0 + c4*4);
            aval[s][0]=mv.x; aval[s][1]=mv.y; aval[s][2]=mv.z; aval[s][3]=mv.w;
        }
        #pragma unroll
        for (int s=0;s<2;s++){
            int idx = t + s*256;
            int r = idx >> 5, c4 = idx & 31;
            float4 wv = *(const float4*)(W + (size_t)(k0 + r)*HID + col0 + c4*4);
            bval[s][0]=wv.x; bval[s][1]=wv.y; bval[s][2]=wv.z; bval[s][3]=wv.w;
        }
    };

    auto storestage = [&](int buf){
        #pragma unroll
        for (int s=0;s<2;s++){
            int idx = t + s*256;
            int r = idx >> 2, c4 = idx & 3;
            __nv_bfloat16 h[4], l[4];
            #pragma unroll
            for (int j=0;j<4;j++){
                h[j] = __float2bfloat16(aval[s][j]);
                l[j] = __float2bfloat16(aval[s][j] - __bfloat162float(h[j]));
            }
            *(uint2*)&Ash[buf][r*ALD + c4*4] = make_uint2(bpack(h[0],h[1]), bpack(h[2],h[3]));
            *(uint2*)&Asl[buf][r*ALD + c4*4] = make_uint2(bpack(l[0],l[1]), bpack(l[2],l[3]));
        }
        #pragma unroll
        for (int s=0;s<2;s++){
            int idx = t + s*256;
            int r = idx >> 5, c4 = idx & 31;
            __nv_bfloat16 h[4], l[4];
            #pragma unroll
            for (int j=0;j<4;j++){
                h[j] = __float2bfloat16(bval[s][j]);
                l[j] = __float2bfloat16(bval[s][j] - __bfloat162float(h[j]));
            }
            *(uint2*)&Bsh[buf][r*BLD + c4*4] = make_uint2(bpack(h[0],h[1]), bpack(h[2],h[3]));
            *(uint2*)&Bsl[buf][r*BLD + c4*4] = make_uint2(bpack(l[0],l[1]), bpack(l[2],l[3]));
        }
    };

    auto compute = [&](int buf){
        const int arow = wm*64 + (lane & 15);
        const int acol = (lane >> 4)*8;
        uint32_t aAddrH = sptr(&Ash[buf][0]) + (uint32_t)((arow*ALD + acol)*2);
        uint32_t aAddrL = sptr(&Asl[buf][0]) + (uint32_t)((arow*ALD + acol)*2);
        const int brow = lane & 15;
        const int bcol = wn*32 + (lane >> 4)*8;
        uint32_t bAddrH = sptr(&Bsh[buf][0]) + (uint32_t)((brow*BLD + bcol)*2);
        uint32_t bAddrL = sptr(&Bsl[buf][0]) + (uint32_t)((brow*BLD + bcol)*2);

        uint32_t A_[4][4], B[4][2], Bl[4][2];
        #pragma unroll
        for (int mi=0; mi<4; mi++)
            ldsm4(A_[mi][0],A_[mi][1],A_[mi][2],A_[mi][3], aAddrH + (uint32_t)(mi*16*ALD*2));
        #pragma unroll
        for (int np=0; np<2; np++)
            ldsm4t(B[2*np][0],B[2*np][1],B[2*np+1][0],B[2*np+1][1],
                   bAddrH + (uint32_t)(np*16*2));
        #pragma unroll
        for (int np=0; np<2; np++)
            ldsm4t(Bl[2*np][0],Bl[2*np][1],Bl[2*np+1][0],Bl[2*np+1][1],
                   bAddrL + (uint32_t)(np*16*2));
        #pragma unroll
        for (int mi=0; mi<4; mi++)
            #pragma unroll
            for (int ni=0; ni<4; ni++)
                mma16816(acc[mi][ni], A_[mi], B[ni][0], B[ni][1]);
        #pragma unroll
        for (int mi=0; mi<4; mi++)
            #pragma unroll
            for (int ni=0; ni<4; ni++)
                mma16816(acc[mi][ni], A_[mi], Bl[ni][0], Bl[ni][1]);
        #pragma unroll
        for (int mi=0; mi<4; mi++)
            ldsm4(A_[mi][0],A_[mi][1],A_[mi][2],A_[mi][3], aAddrL + (uint32_t)(mi*16*ALD*2));
        #pragma unroll
        for (int mi=0; mi<4; mi++)
            #pragma unroll
            for (int ni=0; ni<4; ni++)
                mma16816(acc[mi][ni], A_[mi], B[ni][0], B[ni][1]);
    };

    const int KS = K/16;
    loadstage(0);
    storestage(0);
    __syncthreads();
    for (int ks=0; ks<KS; ks++){
        if (ks+1 < KS) loadstage(ks+1);
        compute(ks & 1);
        if (ks+1 < KS) storestage((ks+1) & 1);
        __syncthreads();
    }

    // epilogue: bias + relu, bf16 stores
    const int gid = lane >> 2, tig = lane & 3;
    #pragma unroll
    for (int ni=0; ni<4; ni++){
        int c = col0 + wn*32 + ni*8 + tig*2;
        float2 bb = *(const float2*)(bias + c);
        #pragma unroll
        for (int mi=0; mi<4; mi++){
            int r = row0 + wm*64 + mi*16 + gid;
            if (r < NN){
                __nv_bfloat162 o = __floats2bfloat162_rn(
                    fmaxf(acc[mi][ni][0] + bb.x, 0.f),
                    fmaxf(acc[mi][ni][1] + bb.y, 0.f));
                *(__nv_bfloat162*)(out + (size_t)r*HID + c) = o;
            }
            int r2 = r + 8;
            if (r2 < NN){
                __nv_bfloat162 o = __floats2bfloat162_rn(
                    fmaxf(acc[mi][ni][2] + bb.x, 0.f),
                    fmaxf(acc[mi][ni][3] + bb.y, 0.f));
                *(__nv_bfloat162*)(out + (size_t)r2*HID + c) = o;
            }
        }
    }
}

// ---------------- multipool (bf16 input) ----------------
__global__ void pool_kernel(const int* __restrict__ batches){
    const __nv_bfloat16* h = g_BA;   // final layer output
    __shared__ int idxs[SUBSZ];
    int t = threadIdx.x, b = blockIdx.x;
    if (t < SUBSZ) idxs[t] = batches[b*SUBSZ + t];
    __syncthreads();
    float s = 0.f, mn = 3.4e38f, mx = -3.4e38f;
    #pragma unroll 8
    for (int m = 0; m < SUBSZ; m++){
        float v = __bfloat162float(h[(size_t)idxs[m]*HID + t]);
        s += v; mn = fminf(mn, v); mx = fmaxf(mx, v);
    }
    float* z = g_Z + (size_t)b*4*HID;
    z[t]         = s;
    z[HID + t]   = s * (1.0f/SUBSZ);
    z[2*HID + t] = mn;
    z[3*HID + t] = mx;
}

// ---------------- readout + BCE ----------------
__global__ void zero_out(float* out){
    if (threadIdx.x == 0 && blockIdx.x == 0) out[0] = 0.f;
}

__global__ __launch_bounds__(256)
void readout8(const float* __restrict__ Wr1, const float* __restrict__ br1,
              const float* __restrict__ Wr2, const float* __restrict__ br2,
              const float* __restrict__ labels, float* out){
    const int b0 = blockIdx.x*8;
    __shared__ float z[8*4*HID];
    int t = threadIdx.x;
    const float4* zg = (const float4*)(g_Z + (size_t)b0*4*HID);
    #pragma unroll
    for (int j = t; j < 8*4*HID/4; j += 256)
        ((float4*)z)[j] = zg[j];
    __syncthreads();

    float bb = br1[t];
    float acc[8];
    #pragma unroll
    for (int j=0;j<8;j++) acc[j] = bb;

    #pragma unroll 8
    for (int k=0;k<4*HID;k++){
        float w = Wr1[(size_t)k*HID + t];
        #pragma unroll
        for (int j=0;j<8;j++) acc[j] += z[j*4*HID + k]*w;
    }
    __syncthreads();
    float wr2 = Wr2[t];
    #pragma unroll
    for (int j=0;j<8;j++) z[j*HID + t] = fmaxf(acc[j], 0.f)*wr2;
    __syncthreads();

    int w = t >> 5, lane = t & 31;
    float s = 0.f;
    #pragma unroll
    for (int q=0;q<8;q++) s += z[w*HID + lane + q*32];
    #pragma unroll
    for (int off=16; off>0; off>>=1) s += __shfl_xor_sync(0xffffffffu, s, off);
    if (lane == 0){
        float p = s + br2[0];
        float l = labels[b0 + w];
        float term = fmaxf(p, 0.f) - p*l + log1pf(expf(-fabsf(p)));
        atomicAdd(out, term * (1.0f/NSUB));
    }
}

// ---------------- launch ----------------
static cudaStream_t g_s2 = nullptr;
static cudaEvent_t  g_evFork = nullptr, g_evJoin = nullptr;

extern "C" void kernel_launch(void* const* d_in, const int* in_sizes, int n_in,
                              void* d_out, int out_size){
    const float* x       = (const float*)d_in[0];
    const int*   esrc    = (const int*)  d_in[1];
    const int*   edst    = (const int*)  d_in[2];
    const float* ew      = (const float*)d_in[3];
    const int*   batches = (const int*)  d_in[4];
    const float* labels  = (const float*)d_in[6];
    const float* W0      = (const float*)d_in[7];
    const float* b0      = (const float*)d_in[8];
    const float* W1      = (const float*)d_in[9];
    const float* b1      = (const float*)d_in[10];
    const float* W2      = (const float*)d_in[11];
    const float* b2      = (const float*)d_in[12];
    const float* eps     = (const float*)d_in[13];
    const float* Wr1     = (const float*)d_in[14];
    const float* br1     = (const float*)d_in[15];
    const float* Wr2     = (const float*)d_in[16];
    const float* br2     = (const float*)d_in[17];
    float* out = (float*)d_out;

    // one-time host resource creation (first call is the uncaptured correctness run)
    if (!g_s2){
        cudaStreamCreateWithFlags(&g_s2, cudaStreamNonBlocking);
        cudaEventCreateWithFlags(&g_evFork, cudaEventDisableTiming);
        cudaEventCreateWithFlags(&g_evJoin, cudaEventDisableTiming);
    }

    // fork: CSR build chain on side stream, prep on main stream
    cudaEventRecord(g_evFork, 0);
    cudaStreamWaitEvent(g_s2, g_evFork, 0);

    // main stream: input prep
    build_h0<<<4096, 256>>>(x);
    scatter_batch<<<(MTOT+255)/256, 256>>>(batches);
    build_w0p<<<(K0*HID+255)/256, 256>>>(W0);

    // side stream: CSR build (by dst)
    zero_degcur<<<(NN+255)/256, 256, 0, g_s2>>>();
    hist_dst<<<(NE+255)/256, 256, 0, g_s2>>>(edst);
    scan_block<<<NBLK, SCAN_B, 0, g_s2>>>();
    scan_bsums<<<1, 256, 0, g_s2>>>();
    scan_add<<<NBLK, SCAN_B, 0, g_s2>>>();
    csr_scatter<<<(NE+255)/256, 256, 0, g_s2>>>(esrc, edst, ew);

    // join
    cudaEventRecord(g_evJoin, g_s2);
    cudaStreamWaitEvent(0, g_evJoin, 0);

    dim3 gemmGrid(2, (NN+127)/128);
    const int gatherGrid = (NN+7)/8;

    // layer 0: 132 live cols (33 units), pad to 160 (40 units)
    csr_gather<<<gatherGrid, 256>>>(0, eps, 0, K0, 33, 40);
    gemm_mma<K0><<<gemmGrid, 256>>>(nullptr, 1, b0, 1);

    // layer 1
    csr_gather<<<gatherGrid, 256>>>(1, eps, 1, HID, 64, 64);
    gemm_mma<HID><<<gemmGrid, 256>>>(W1, 0, b1, 2);

    // layer 2
    csr_gather<<<gatherGrid, 256>>>(2, eps, 2, HID, 64, 64);
    gemm_mma<HID><<<gemmGrid, 256>>>(W2, 0, b2, 1);

    pool_kernel<<<NSUB, HID>>>(batches);
    zero_out<<<1, 32>>>(out);
    readout8<<<NSUB/8, 256>>>(Wr1, br1, Wr2, br2, labels, out);
}

// round 7
// speedup vs baseline: 2.4853x; 1.1053x over previous
#include <cuda_runtime.h>
#include <cuda_bf16.h>
#include <cuda_fp16.h>
#include <math.h>
#include <stdint.h>

#define NN    50000
#define FEAT  128
#define HID   256
#define K0    160        // layer-0 K (129 live -> 132 used) padded to 160
#define NE    800000
#define NSUB  512
#define SUBSZ 64
#define MTOT  (NSUB*SUBSZ)

#define SCAN_B 256
#define NBLK   ((NN + SCAN_B - 1) / SCAN_B)   // 196

// ---------------- scratch (device globals; no allocation allowed) ----------------
__device__ __align__(16) float          g_MSG[NN*HID];   // f32 GEMM A (160-col view for L0)
__device__ __align__(16) __nv_bfloat16  g_B0 [NN*K0];    // bf16 h0
__device__ __align__(16) __nv_bfloat16  g_BA [NN*HID];   // bf16 h (layers)
__device__ __align__(16) __nv_bfloat16  g_BB [NN*HID];
__device__ __align__(16) float          g_W0p[K0*HID];   // zero-padded W0
__device__ __align__(16) float          g_Z  [NSUB*4*HID];
// CSR scratch
__device__ int   g_deg [NN];
__device__ int   g_cur [NN];
__device__ int   g_off [NN+1];
__device__ int   g_bsum[NBLK];
__device__ int   g_csrc[NE];
__device__ float g_cw  [NE];

__device__ __forceinline__ __nv_bfloat16* gbuf16(int id){
    switch(id){
        case 0: return g_B0;
        case 1: return g_BA;
        default: return g_BB;
    }
}

// ---------------- setup ----------------
__global__ void build_h0(const float* __restrict__ x){
    int idx = blockIdx.x*blockDim.x + threadIdx.x;
    const int total = NN*K0;
    for (; idx < total; idx += gridDim.x*blockDim.x){
        int i = idx / K0;
        int c = idx - i*K0;
        g_B0[idx] = (c < FEAT) ? __float2bfloat16(x[i*FEAT + c]) : __float2bfloat16(0.f);
    }
}

__global__ void scatter_batch(const int* __restrict__ batches){
    int m = blockIdx.x*blockDim.x + threadIdx.x;
    if (m < MTOT) g_B0[(size_t)batches[m]*K0 + FEAT] = __float2bfloat16(1.0f);
}

__global__ void build_w0p(const float* __restrict__ W0){
    int idx = blockIdx.x*blockDim.x + threadIdx.x;
    if (idx < K0*HID){
        int r = idx / HID;
        int c = idx - r*HID;
        g_W0p[idx] = (r < FEAT+1) ? W0[r*HID + c] : 0.0f;
    }
}

// ---------------- CSR build ----------------
__global__ void zero_degcur(){
    int i = blockIdx.x*blockDim.x + threadIdx.x;
    if (i < NN){ g_deg[i] = 0; g_cur[i] = 0; }
}

__global__ void hist_dst(const int* __restrict__ dst){
    int e = blockIdx.x*blockDim.x + threadIdx.x;
    if (e < NE) atomicAdd(&g_deg[dst[e]], 1);
}

__global__ void scan_block(){
    __shared__ int sh[SCAN_B];
    int i = blockIdx.x*SCAN_B + threadIdx.x;
    int v = (i < NN) ? g_deg[i] : 0;
    sh[threadIdx.x] = v;
    __syncthreads();
    #pragma unroll
    for (int off = 1; off < SCAN_B; off <<= 1){
        int add = (threadIdx.x >= off) ? sh[threadIdx.x - off] : 0;
        __syncthreads();
        sh[threadIdx.x] += add;
        __syncthreads();
    }
    if (i < NN) g_off[i] = sh[threadIdx.x] - v;
    if (threadIdx.x == SCAN_B-1) g_bsum[blockIdx.x] = sh[SCAN_B-1];
}

__global__ void scan_bsums(){
    __shared__ int sh[256];
    int t = threadIdx.x;
    int v = (t < NBLK) ? g_bsum[t] : 0;
    sh[t] = v;
    __syncthreads();
    #pragma unroll
    for (int off = 1; off < 256; off <<= 1){
        int add = (t >= off) ? sh[t - off] : 0;
        __syncthreads();
        sh[t] += add;
        __syncthreads();
    }
    if (t < NBLK) g_bsum[t] = sh[t] - v;
}

__global__ void scan_add(){
    int i = blockIdx.x*SCAN_B + threadIdx.x;
    if (i < NN) g_off[i] += g_bsum[blockIdx.x];
    if (i == 0) g_off[NN] = NE;
}

__global__ void csr_scatter(const int* __restrict__ src, const int* __restrict__ dst,
                            const float* __restrict__ ew){
    int e = blockIdx.x*blockDim.x + threadIdx.x;
    if (e < NE){
        int d = dst[e];
        int pos = g_off[d] + atomicAdd(&g_cur[d], 1);
        g_csrc[pos] = src[e];
        g_cw[pos]   = ew[e];
    }
}

// ---------------- gather (bf16 inputs, f32 accumulate, edge-unroll x4) ----------------
__device__ __forceinline__ void facc(float4& a, float w, uint2 u){
    float2 f0 = __bfloat1622float2(*(__nv_bfloat162*)&u.x);
    float2 f1 = __bfloat1622float2(*(__nv_bfloat162*)&u.y);
    a.x += w*f0.x; a.y += w*f0.y; a.z += w*f1.x; a.w += w*f1.y;
}

__global__ __launch_bounds__(256)
void csr_gather(int hsel, const float* __restrict__ eps, int ei, int ld, int w4r, int w4p){
    const __nv_bfloat16* h = gbuf16(hsel);
    int n = blockIdx.x*8 + (threadIdx.x >> 5);
    if (n >= NN) return;
    int lane = threadIdx.x & 31;
    int s0 = g_off[n], s1 = g_off[n+1];

    const bool a0 = (lane      < w4r);
    const bool a1 = (lane + 32 < w4r);
    float4 acc0 = make_float4(0.f,0.f,0.f,0.f);
    float4 acc1 = make_float4(0.f,0.f,0.f,0.f);

    int e = s0;
    for (; e + 4 <= s1; e += 4){
        int   si[4]; float wi[4];
        #pragma unroll
        for (int j=0;j<4;j++){
            si[j] = __ldg(&g_csrc[e+j]);
            wi[j] = __ldg(&g_cw[e+j]);
        }
        uint2 u0[4], u1[4];
        #pragma unroll
        for (int j=0;j<4;j++){
            const uint2* hs = (const uint2*)(h + (size_t)si[j]*ld);
            if (a0) u0[j] = __ldg(&hs[lane]);
            if (a1) u1[j] = __ldg(&hs[lane+32]);
        }
        #pragma unroll
        for (int j=0;j<4;j++){
            if (a0) facc(acc0, wi[j], u0[j]);
            if (a1) facc(acc1, wi[j], u1[j]);
        }
    }
    for (; e < s1; e++){
        int   s = __ldg(&g_csrc[e]);
        float w = __ldg(&g_cw[e]);
        const uint2* hs = (const uint2*)(h + (size_t)s*ld);
        if (a0){ uint2 u = __ldg(&hs[lane]);    facc(acc0, w, u); }
        if (a1){ uint2 u = __ldg(&hs[lane+32]); facc(acc1, w, u); }
    }

    const float ep = 1.0f + eps[ei];
    const uint2* hn = (const uint2*)(h + (size_t)n*ld);
    float4* mrow = (float4*)(g_MSG + (size_t)n*ld);
    if (a0){
        uint2 u = __ldg(&hn[lane]);
        facc(acc0, ep, u);
        mrow[lane] = acc0;
    }
    if (a1){
        uint2 u = __ldg(&hn[lane+32]);
        facc(acc1, ep, u);
        mrow[lane+32] = acc1;
    } else if (lane + 32 < w4p){
        mrow[lane+32] = make_float4(0.f,0.f,0.f,0.f);
    }
}

// ---------------- tensor-core GIN GEMM: outb16 = relu(MSG @ W + b) ------
// fp16 2-product split: A = ah + al (fp16 pair), B = bh (fp16).
// C = ah*bh + al*bh; residual = A*(B - bh) ~ 2^-12 relative.
__device__ __forceinline__ uint32_t sptr(const void* p){
    return (uint32_t)__cvta_generic_to_shared(p);
}
__device__ __forceinline__ void ldsm4(uint32_t& r0,uint32_t& r1,uint32_t& r2,uint32_t& r3, uint32_t a){
    asm volatile("ldmatrix.sync.aligned.m8n8.x4.shared.b16 {%0,%1,%2,%3},[%4];"
                 : "=r"(r0),"=r"(r1),"=r"(r2),"=r"(r3) : "r"(a));
}
__device__ __forceinline__ void ldsm4t(uint32_t& r0,uint32_t& r1,uint32_t& r2,uint32_t& r3, uint32_t a){
    asm volatile("ldmatrix.sync.aligned.m8n8.x4.trans.shared.b16 {%0,%1,%2,%3},[%4];"
                 : "=r"(r0),"=r"(r1),"=r"(r2),"=r"(r3) : "r"(a));
}
__device__ __forceinline__ void mma16816h(float* c, const uint32_t* a, uint32_t b0, uint32_t b1){
    asm volatile("mma.sync.aligned.m16n8k16.row.col.f32.f16.f16.f32 "
                 "{%0,%1,%2,%3},{%4,%5,%6,%7},{%8,%9},{%0,%1,%2,%3};"
                 : "+f"(c[0]),"+f"(c[1]),"+f"(c[2]),"+f"(c[3])
                 : "r"(a[0]),"r"(a[1]),"r"(a[2]),"r"(a[3]),"r"(b0),"r"(b1));
}
__device__ __forceinline__ uint32_t hpack(__half a, __half b){
    __half2 t = __halves2half2(a,b);
    return *reinterpret_cast<uint32_t*>(&t);
}

#define ALD 24
#define BLD 136

template<int K>
__global__ __launch_bounds__(256)
void gemm_mma(const float* __restrict__ Wp, int useW0p,
              const float* __restrict__ bias, int osel){
    const float* A = g_MSG;
    const float* W = useW0p ? g_W0p : Wp;
    __nv_bfloat16* out = gbuf16(osel);

    __shared__ __half Ash[2][128*ALD];
    __shared__ __half Asl[2][128*ALD];
    __shared__ __half Bsh[2][16*BLD];

    const int t = threadIdx.x;
    const int warp = t >> 5, lane = t & 31;
    const int wm = warp >> 2, wn = warp & 3;
    const int row0 = blockIdx.y*128, col0 = blockIdx.x*128;

    float acc[4][4][4];
    #pragma unroll
    for (int i=0;i<4;i++)
        #pragma unroll
        for (int j=0;j<4;j++)
            #pragma unroll
            for (int q=0;q<4;q++) acc[i][j][q]=0.f;

    float aval[2][4];
    float bval[2][4];

    auto loadstage = [&](int ks){
        const int k0 = ks*16;
        #pragma unroll
        for (int s=0;s<2;s++){
            int idx = t + s*256;
            int r = idx >> 2, c4 = idx & 3;
            int gr = row0 + r;
            float4 mv = make_float4(0.f,0.f,0.f,0.f);
            if (gr < NN)
                mv = *(const float4*)(A + (size_t)gr*K + k0 + c4*4);
            aval[s][0]=mv.x; aval[s][1]=mv.y; aval[s][2]=mv.z; aval[s][3]=mv.w;
        }
        #pragma unroll
        for (int s=0;s<2;s++){
            int idx = t + s*256;
            int r = idx >> 5, c4 = idx & 31;
            float4 wv = *(const float4*)(W + (size_t)(k0 + r)*HID + col0 + c4*4);
            bval[s][0]=wv.x; bval[s][1]=wv.y; bval[s][2]=wv.z; bval[s][3]=wv.w;
        }
    };

    auto storestage = [&](int buf){
        #pragma unroll
        for (int s=0;s<2;s++){
            int idx = t + s*256;
            int r = idx >> 2, c4 = idx & 3;
            __half h[4], l[4];
            #pragma unroll
            for (int j=0;j<4;j++){
                h[j] = __float2half(aval[s][j]);
                l[j] = __float2half(aval[s][j] - __half2float(h[j]));
            }
            *(uint2*)&Ash[buf][r*ALD + c4*4] = make_uint2(hpack(h[0],h[1]), hpack(h[2],h[3]));
            *(uint2*)&Asl[buf][r*ALD + c4*4] = make_uint2(hpack(l[0],l[1]), hpack(l[2],l[3]));
        }
        #pragma unroll
        for (int s=0;s<2;s++){
            int idx = t + s*256;
            int r = idx >> 5, c4 = idx & 31;
            __half h[4];
            #pragma unroll
            for (int j=0;j<4;j++)
                h[j] = __float2half(bval[s][j]);
            *(uint2*)&Bsh[buf][r*BLD + c4*4] = make_uint2(hpack(h[0],h[1]), hpack(h[2],h[3]));
        }
    };

    auto compute = [&](int buf){
        const int arow = wm*64 + (lane & 15);
        const int acol = (lane >> 4)*8;
        uint32_t aAddrH = sptr(&Ash[buf][0]) + (uint32_t)((arow*ALD + acol)*2);
        uint32_t aAddrL = sptr(&Asl[buf][0]) + (uint32_t)((arow*ALD + acol)*2);
        const int brow = lane & 15;
        const int bcol = wn*32 + (lane >> 4)*8;
        uint32_t bAddrH = sptr(&Bsh[buf][0]) + (uint32_t)((brow*BLD + bcol)*2);

        uint32_t A_[4][4], B[4][2];
        #pragma unroll
        for (int mi=0; mi<4; mi++)
            ldsm4(A_[mi][0],A_[mi][1],A_[mi][2],A_[mi][3], aAddrH + (uint32_t)(mi*16*ALD*2));
        #pragma unroll
        for (int np=0; np<2; np++)
            ldsm4t(B[2*np][0],B[2*np][1],B[2*np+1][0],B[2*np+1][1],
                   bAddrH + (uint32_t)(np*16*2));
        // hi * B
        #pragma unroll
        for (int mi=0; mi<4; mi++)
            #pragma unroll
            for (int ni=0; ni<4; ni++)
                mma16816h(acc[mi][ni], A_[mi], B[ni][0], B[ni][1]);
        // lo * B
        #pragma unroll
        for (int mi=0; mi<4; mi++)
            ldsm4(A_[mi][0],A_[mi][1],A_[mi][2],A_[mi][3], aAddrL + (uint32_t)(mi*16*ALD*2));
        #pragma unroll
        for (int mi=0; mi<4; mi++)
            #pragma unroll
            for (int ni=0; ni<4; ni++)
                mma16816h(acc[mi][ni], A_[mi], B[ni][0], B[ni][1]);
    };

    const int KS = K/16;
    loadstage(0);
    storestage(0);
    __syncthreads();
    for (int ks=0; ks<KS; ks++){
        if (ks+1 < KS) loadstage(ks+1);
        compute(ks & 1);
        if (ks+1 < KS) storestage((ks+1) & 1);
        __syncthreads();
    }

    // epilogue: bias + relu, bf16 stores
    const int gid = lane >> 2, tig = lane & 3;
    #pragma unroll
    for (int ni=0; ni<4; ni++){
        int c = col0 + wn*32 + ni*8 + tig*2;
        float2 bb = *(const float2*)(bias + c);
        #pragma unroll
        for (int mi=0; mi<4; mi++){
            int r = row0 + wm*64 + mi*16 + gid;
            if (r < NN){
                __nv_bfloat162 o = __floats2bfloat162_rn(
                    fmaxf(acc[mi][ni][0] + bb.x, 0.f),
                    fmaxf(acc[mi][ni][1] + bb.y, 0.f));
                *(__nv_bfloat162*)(out + (size_t)r*HID + c) = o;
            }
            int r2 = r + 8;
            if (r2 < NN){
                __nv_bfloat162 o = __floats2bfloat162_rn(
                    fmaxf(acc[mi][ni][2] + bb.x, 0.f),
                    fmaxf(acc[mi][ni][3] + bb.y, 0.f));
                *(__nv_bfloat162*)(out + (size_t)r2*HID + c) = o;
            }
        }
    }
}

// ---------------- multipool (bf16 input) ----------------
__global__ void pool_kernel(const int* __restrict__ batches){
    const __nv_bfloat16* h = g_BA;   // final layer output
    __shared__ int idxs[SUBSZ];
    int t = threadIdx.x, b = blockIdx.x;
    if (t < SUBSZ) idxs[t] = batches[b*SUBSZ + t];
    __syncthreads();
    float s = 0.f, mn = 3.4e38f, mx = -3.4e38f;
    #pragma unroll 8
    for (int m = 0; m < SUBSZ; m++){
        float v = __bfloat162float(h[(size_t)idxs[m]*HID + t]);
        s += v; mn = fminf(mn, v); mx = fmaxf(mx, v);
    }
    float* z = g_Z + (size_t)b*4*HID;
    z[t]         = s;
    z[HID + t]   = s * (1.0f/SUBSZ);
    z[2*HID + t] = mn;
    z[3*HID + t] = mx;
}

// ---------------- readout + BCE ----------------
__global__ void zero_out(float* out){
    if (threadIdx.x == 0 && blockIdx.x == 0) out[0] = 0.f;
}

__global__ __launch_bounds__(256)
void readout8(const float* __restrict__ Wr1, const float* __restrict__ br1,
              const float* __restrict__ Wr2, const float* __restrict__ br2,
              const float* __restrict__ labels, float* out){
    const int b0 = blockIdx.x*8;
    __shared__ float z[8*4*HID];
    int t = threadIdx.x;
    const float4* zg = (const float4*)(g_Z + (size_t)b0*4*HID);
    #pragma unroll
    for (int j = t; j < 8*4*HID/4; j += 256)
        ((float4*)z)[j] = zg[j];
    __syncthreads();

    float bb = br1[t];
    float acc[8];
    #pragma unroll
    for (int j=0;j<8;j++) acc[j] = bb;

    #pragma unroll 8
    for (int k=0;k<4*HID;k++){
        float w = Wr1[(size_t)k*HID + t];
        #pragma unroll
        for (int j=0;j<8;j++) acc[j] += z[j*4*HID + k]*w;
    }
    __syncthreads();
    float wr2 = Wr2[t];
    #pragma unroll
    for (int j=0;j<8;j++) z[j*HID + t] = fmaxf(acc[j], 0.f)*wr2;
    __syncthreads();

    int w = t >> 5, lane = t & 31;
    float s = 0.f;
    #pragma unroll
    for (int q=0;q<8;q++) s += z[w*HID + lane + q*32];
    #pragma unroll
    for (int off=16; off>0; off>>=1) s += __shfl_xor_sync(0xffffffffu, s, off);
    if (lane == 0){
        float p = s + br2[0];
        float l = labels[b0 + w];
        float term = fmaxf(p, 0.f) - p*l + log1pf(expf(-fabsf(p)));
        atomicAdd(out, term * (1.0f/NSUB));
    }
}

// ---------------- launch ----------------
static cudaStream_t g_s2 = nullptr;
static cudaEvent_t  g_evFork = nullptr, g_evJoin = nullptr;

extern "C" void kernel_launch(void* const* d_in, const int* in_sizes, int n_in,
                              void* d_out, int out_size){
    const float* x       = (const float*)d_in[0];
    const int*   esrc    = (const int*)  d_in[1];
    const int*   edst    = (const int*)  d_in[2];
    const float* ew      = (const float*)d_in[3];
    const int*   batches = (const int*)  d_in[4];
    const float* labels  = (const float*)d_in[6];
    const float* W0      = (const float*)d_in[7];
    const float* b0      = (const float*)d_in[8];
    const float* W1      = (const float*)d_in[9];
    const float* b1      = (const float*)d_in[10];
    const float* W2      = (const float*)d_in[11];
    const float* b2      = (const float*)d_in[12];
    const float* eps     = (const float*)d_in[13];
    const float* Wr1     = (const float*)d_in[14];
    const float* br1     = (const float*)d_in[15];
    const float* Wr2     = (const float*)d_in[16];
    const float* br2     = (const float*)d_in[17];
    float* out = (float*)d_out;

    if (!g_s2){
        cudaStreamCreateWithFlags(&g_s2, cudaStreamNonBlocking);
        cudaEventCreateWithFlags(&g_evFork, cudaEventDisableTiming);
        cudaEventCreateWithFlags(&g_evJoin, cudaEventDisableTiming);
    }

    cudaEventRecord(g_evFork, 0);
    cudaStreamWaitEvent(g_s2, g_evFork, 0);

    // main stream: input prep
    build_h0<<<4096, 256>>>(x);
    scatter_batch<<<(MTOT+255)/256, 256>>>(batches);
    build_w0p<<<(K0*HID+255)/256, 256>>>(W0);

    // side stream: CSR build (by dst)
    zero_degcur<<<(NN+255)/256, 256, 0, g_s2>>>();
    hist_dst<<<(NE+255)/256, 256, 0, g_s2>>>(edst);
    scan_block<<<NBLK, SCAN_B, 0, g_s2>>>();
    scan_bsums<<<1, 256, 0, g_s2>>>();
    scan_add<<<NBLK, SCAN_B, 0, g_s2>>>();
    csr_scatter<<<(NE+255)/256, 256, 0, g_s2>>>(esrc, edst, ew);

    cudaEventRecord(g_evJoin, g_s2);
    cudaStreamWaitEvent(0, g_evJoin, 0);

    dim3 gemmGrid(2, (NN+127)/128);
    const int gatherGrid = (NN+7)/8;

    // layer 0
    csr_gather<<<gatherGrid, 256>>>(0, eps, 0, K0, 33, 40);
    gemm_mma<K0><<<gemmGrid, 256>>>(nullptr, 1, b0, 1);

    // layer 1
    csr_gather<<<gatherGrid, 256>>>(1, eps, 1, HID, 64, 64);
    gemm_mma<HID><<<gemmGrid, 256>>>(W1, 0, b1, 2);

    // layer 2
    csr_gather<<<gatherGrid, 256>>>(2, eps, 2, HID, 64, 64);
    gemm_mma<HID><<<gemmGrid, 256>>>(W2, 0, b2, 1);

    pool_kernel<<<NSUB, HID>>>(batches);
    zero_out<<<1, 32>>>(out);
    readout8<<<NSUB/8, 256>>>(Wr1, br1, Wr2, br2, labels, out);
}

// round 8
// speedup vs baseline: 2.7062x; 1.0889x over previous
#include <cuda_runtime.h>
#include <cuda_bf16.h>
#include <cuda_fp16.h>
#include <math.h>
#include <stdint.h>

#define NN    50000
#define FEAT  128
#define HID   256
#define K0    160        // layer-0 K (129 live -> 132 used) padded to 160
#define NE    800000
#define NSUB  512
#define SUBSZ 64
#define MTOT  (NSUB*SUBSZ)

#define SCAN_B 256
#define NBLK   ((NN + SCAN_B - 1) / SCAN_B)   // 196

// ---------------- scratch (device globals; no allocation allowed) ----------------
__device__ __align__(16) __half         g_MSG[NN*HID];   // fp16 GEMM A (160-col view for L0)
__device__ __align__(16) __nv_bfloat16  g_B0 [NN*K0];    // bf16 h0
__device__ __align__(16) __nv_bfloat16  g_BA [NN*HID];   // bf16 h (layers)
__device__ __align__(16) __nv_bfloat16  g_BB [NN*HID];
__device__ __align__(16) float          g_W0p[K0*HID];   // zero-padded W0
__device__ __align__(16) float          g_Z  [NSUB*4*HID];
// CSR scratch
__device__ int   g_deg [NN];
__device__ int   g_cur [NN];
__device__ int   g_off [NN+1];
__device__ int   g_bsum[NBLK];
__device__ int   g_csrc[NE];
__device__ float g_cw  [NE];

__device__ __forceinline__ __nv_bfloat16* gbuf16(int id){
    switch(id){
        case 0: return g_B0;
        case 1: return g_BA;
        default: return g_BB;
    }
}

// ---------------- setup ----------------
__global__ void build_h0(const float* __restrict__ x){
    int idx = blockIdx.x*blockDim.x + threadIdx.x;
    const int total = NN*K0;
    for (; idx < total; idx += gridDim.x*blockDim.x){
        int i = idx / K0;
        int c = idx - i*K0;
        g_B0[idx] = (c < FEAT) ? __float2bfloat16(x[i*FEAT + c]) : __float2bfloat16(0.f);
    }
}

__global__ void scatter_batch(const int* __restrict__ batches){
    int m = blockIdx.x*blockDim.x + threadIdx.x;
    if (m < MTOT) g_B0[(size_t)batches[m]*K0 + FEAT] = __float2bfloat16(1.0f);
}

__global__ void build_w0p(const float* __restrict__ W0){
    int idx = blockIdx.x*blockDim.x + threadIdx.x;
    if (idx < K0*HID){
        int r = idx / HID;
        int c = idx - r*HID;
        g_W0p[idx] = (r < FEAT+1) ? W0[r*HID + c] : 0.0f;
    }
}

// ---------------- CSR build ----------------
__global__ void zero_degcur(){
    int i = blockIdx.x*blockDim.x + threadIdx.x;
    if (i < NN){ g_deg[i] = 0; g_cur[i] = 0; }
}

__global__ void hist_dst(const int* __restrict__ dst){
    int e = blockIdx.x*blockDim.x + threadIdx.x;
    if (e < NE) atomicAdd(&g_deg[dst[e]], 1);
}

__global__ void scan_block(){
    __shared__ int sh[SCAN_B];
    int i = blockIdx.x*SCAN_B + threadIdx.x;
    int v = (i < NN) ? g_deg[i] : 0;
    sh[threadIdx.x] = v;
    __syncthreads();
    #pragma unroll
    for (int off = 1; off < SCAN_B; off <<= 1){
        int add = (threadIdx.x >= off) ? sh[threadIdx.x - off] : 0;
        __syncthreads();
        sh[threadIdx.x] += add;
        __syncthreads();
    }
    if (i < NN) g_off[i] = sh[threadIdx.x] - v;
    if (threadIdx.x == SCAN_B-1) g_bsum[blockIdx.x] = sh[SCAN_B-1];
}

__global__ void scan_bsums(){
    __shared__ int sh[256];
    int t = threadIdx.x;
    int v = (t < NBLK) ? g_bsum[t] : 0;
    sh[t] = v;
    __syncthreads();
    #pragma unroll
    for (int off = 1; off < 256; off <<= 1){
        int add = (t >= off) ? sh[t - off] : 0;
        __syncthreads();
        sh[t] += add;
        __syncthreads();
    }
    if (t < NBLK) g_bsum[t] = sh[t] - v;
}

__global__ void scan_add(){
    int i = blockIdx.x*SCAN_B + threadIdx.x;
    if (i < NN) g_off[i] += g_bsum[blockIdx.x];
    if (i == 0) g_off[NN] = NE;
}

__global__ void csr_scatter(const int* __restrict__ src, const int* __restrict__ dst,
                            const float* __restrict__ ew){
    int e = blockIdx.x*blockDim.x + threadIdx.x;
    if (e < NE){
        int d = dst[e];
        int pos = g_off[d] + atomicAdd(&g_cur[d], 1);
        g_csrc[pos] = src[e];
        g_cw[pos]   = ew[e];
    }
}

// ---------------- gather (bf16 inputs, f32 accumulate, fp16 output) ----------------
__device__ __forceinline__ void facc(float4& a, float w, uint2 u){
    float2 f0 = __bfloat1622float2(*(__nv_bfloat162*)&u.x);
    float2 f1 = __bfloat1622float2(*(__nv_bfloat162*)&u.y);
    a.x += w*f0.x; a.y += w*f0.y; a.z += w*f1.x; a.w += w*f1.y;
}
__device__ __forceinline__ uint2 f4toh4(float4 a){
    __half2 lo = __floats2half2_rn(a.x, a.y);
    __half2 hi = __floats2half2_rn(a.z, a.w);
    return make_uint2(*(uint32_t*)&lo, *(uint32_t*)&hi);
}

__global__ __launch_bounds__(256)
void csr_gather(int hsel, const float* __restrict__ eps, int ei, int ld, int w4r, int w4p){
    const __nv_bfloat16* h = gbuf16(hsel);
    int n = blockIdx.x*8 + (threadIdx.x >> 5);
    if (n >= NN) return;
    int lane = threadIdx.x & 31;
    int s0 = g_off[n], s1 = g_off[n+1];

    const bool a0 = (lane      < w4r);
    const bool a1 = (lane + 32 < w4r);
    float4 acc0 = make_float4(0.f,0.f,0.f,0.f);
    float4 acc1 = make_float4(0.f,0.f,0.f,0.f);

    int e = s0;
    for (; e + 4 <= s1; e += 4){
        int   si[4]; float wi[4];
        #pragma unroll
        for (int j=0;j<4;j++){
            si[j] = __ldg(&g_csrc[e+j]);
            wi[j] = __ldg(&g_cw[e+j]);
        }
        uint2 u0[4], u1[4];
        #pragma unroll
        for (int j=0;j<4;j++){
            const uint2* hs = (const uint2*)(h + (size_t)si[j]*ld);
            if (a0) u0[j] = __ldg(&hs[lane]);
            if (a1) u1[j] = __ldg(&hs[lane+32]);
        }
        #pragma unroll
        for (int j=0;j<4;j++){
            if (a0) facc(acc0, wi[j], u0[j]);
            if (a1) facc(acc1, wi[j], u1[j]);
        }
    }
    for (; e < s1; e++){
        int   s = __ldg(&g_csrc[e]);
        float w = __ldg(&g_cw[e]);
        const uint2* hs = (const uint2*)(h + (size_t)s*ld);
        if (a0){ uint2 u = __ldg(&hs[lane]);    facc(acc0, w, u); }
        if (a1){ uint2 u = __ldg(&hs[lane+32]); facc(acc1, w, u); }
    }

    const float ep = 1.0f + eps[ei];
    const uint2* hn = (const uint2*)(h + (size_t)n*ld);
    uint2* mrow = (uint2*)(g_MSG + (size_t)n*ld);
    if (a0){
        uint2 u = __ldg(&hn[lane]);
        facc(acc0, ep, u);
        mrow[lane] = f4toh4(acc0);
    }
    if (a1){
        uint2 u = __ldg(&hn[lane+32]);
        facc(acc1, ep, u);
        mrow[lane+32] = f4toh4(acc1);
    } else if (lane + 32 < w4p){
        mrow[lane+32] = make_uint2(0u, 0u);
    }
}

// ---------------- tensor-core GIN GEMM: outb16 = relu(MSG @ W + b) ------
// pure fp16 single-product (A fp16, B fp16, f32 accumulate)
__device__ __forceinline__ uint32_t sptr(const void* p){
    return (uint32_t)__cvta_generic_to_shared(p);
}
__device__ __forceinline__ void ldsm4(uint32_t& r0,uint32_t& r1,uint32_t& r2,uint32_t& r3, uint32_t a){
    asm volatile("ldmatrix.sync.aligned.m8n8.x4.shared.b16 {%0,%1,%2,%3},[%4];"
                 : "=r"(r0),"=r"(r1),"=r"(r2),"=r"(r3) : "r"(a));
}
__device__ __forceinline__ void ldsm4t(uint32_t& r0,uint32_t& r1,uint32_t& r2,uint32_t& r3, uint32_t a){
    asm volatile("ldmatrix.sync.aligned.m8n8.x4.trans.shared.b16 {%0,%1,%2,%3},[%4];"
                 : "=r"(r0),"=r"(r1),"=r"(r2),"=r"(r3) : "r"(a));
}
__device__ __forceinline__ void mma16816h(float* c, const uint32_t* a, uint32_t b0, uint32_t b1){
    asm volatile("mma.sync.aligned.m16n8k16.row.col.f32.f16.f16.f32 "
                 "{%0,%1,%2,%3},{%4,%5,%6,%7},{%8,%9},{%0,%1,%2,%3};"
                 : "+f"(c[0]),"+f"(c[1]),"+f"(c[2]),"+f"(c[3])
                 : "r"(a[0]),"r"(a[1]),"r"(a[2]),"r"(a[3]),"r"(b0),"r"(b1));
}
__device__ __forceinline__ uint32_t hpack(__half a, __half b){
    __half2 t = __halves2half2(a,b);
    return *reinterpret_cast<uint32_t*>(&t);
}

#define ALD 24
#define BLD 136

template<int K>
__global__ __launch_bounds__(256)
void gemm_mma(const float* __restrict__ Wp, int useW0p,
              const float* __restrict__ bias, int osel){
    const __half* A = g_MSG;
    const float*  W = useW0p ? g_W0p : Wp;
    __nv_bfloat16* out = gbuf16(osel);

    __shared__ __half Ash[2][128*ALD];
    __shared__ __half Bsh[2][16*BLD];

    const int t = threadIdx.x;
    const int warp = t >> 5, lane = t & 31;
    const int wm = warp >> 2, wn = warp & 3;
    const int row0 = blockIdx.y*128, col0 = blockIdx.x*128;

    float acc[4][4][4];
    #pragma unroll
    for (int i=0;i<4;i++)
        #pragma unroll
        for (int j=0;j<4;j++)
            #pragma unroll
            for (int q=0;q<4;q++) acc[i][j][q]=0.f;

    uint4 aval;          // 8 fp16 — raw copy, no conversion
    float bval[2][4];

    // A tile 128x16 halves: thread t -> row t>>1, half-offset (t&1)*8
    const int ar  = t >> 1, ac8 = (t & 1)*8;

    auto loadstage = [&](int ks){
        const int k0 = ks*16;
        int gr = row0 + ar;
        aval = make_uint4(0u,0u,0u,0u);
        if (gr < NN)
            aval = *(const uint4*)(A + (size_t)gr*K + k0 + ac8);
        #pragma unroll
        for (int s=0;s<2;s++){
            int idx = t + s*256;
            int r = idx >> 5, c4 = idx & 31;
            float4 wv = *(const float4*)(W + (size_t)(k0 + r)*HID + col0 + c4*4);
            bval[s][0]=wv.x; bval[s][1]=wv.y; bval[s][2]=wv.z; bval[s][3]=wv.w;
        }
    };

    auto storestage = [&](int buf){
        *(uint4*)&Ash[buf][ar*ALD + ac8] = aval;
        #pragma unroll
        for (int s=0;s<2;s++){
            int idx = t + s*256;
            int r = idx >> 5, c4 = idx & 31;
            __half h[4];
            #pragma unroll
            for (int j=0;j<4;j++)
                h[j] = __float2half(bval[s][j]);
            *(uint2*)&Bsh[buf][r*BLD + c4*4] = make_uint2(hpack(h[0],h[1]), hpack(h[2],h[3]));
        }
    };

    auto compute = [&](int buf){
        const int arow = wm*64 + (lane & 15);
        const int acol = (lane >> 4)*8;
        uint32_t aAddrH = sptr(&Ash[buf][0]) + (uint32_t)((arow*ALD + acol)*2);
        const int brow = lane & 15;
        const int bcol = wn*32 + (lane >> 4)*8;
        uint32_t bAddrH = sptr(&Bsh[buf][0]) + (uint32_t)((brow*BLD + bcol)*2);

        uint32_t A_[4][4], B[4][2];
        #pragma unroll
        for (int mi=0; mi<4; mi++)
            ldsm4(A_[mi][0],A_[mi][1],A_[mi][2],A_[mi][3], aAddrH + (uint32_t)(mi*16*ALD*2));
        #pragma unroll
        for (int np=0; np<2; np++)
            ldsm4t(B[2*np][0],B[2*np][1],B[2*np+1][0],B[2*np+1][1],
                   bAddrH + (uint32_t)(np*16*2));
        #pragma unroll
        for (int mi=0; mi<4; mi++)
            #pragma unroll
            for (int ni=0; ni<4; ni++)
                mma16816h(acc[mi][ni], A_[mi], B[ni][0], B[ni][1]);
    };

    const int KS = K/16;
    loadstage(0);
    storestage(0);
    __syncthreads();
    for (int ks=0; ks<KS; ks++){
        if (ks+1 < KS) loadstage(ks+1);
        compute(ks & 1);
        if (ks+1 < KS) storestage((ks+1) & 1);
        __syncthreads();
    }

    // epilogue: bias + relu, bf16 stores
    const int gid = lane >> 2, tig = lane & 3;
    #pragma unroll
    for (int ni=0; ni<4; ni++){
        int c = col0 + wn*32 + ni*8 + tig*2;
        float2 bb = *(const float2*)(bias + c);
        #pragma unroll
        for (int mi=0; mi<4; mi++){
            int r = row0 + wm*64 + mi*16 + gid;
            if (r < NN){
                __nv_bfloat162 o = __floats2bfloat162_rn(
                    fmaxf(acc[mi][ni][0] + bb.x, 0.f),
                    fmaxf(acc[mi][ni][1] + bb.y, 0.f));
                *(__nv_bfloat162*)(out + (size_t)r*HID + c) = o;
            }
            int r2 = r + 8;
            if (r2 < NN){
                __nv_bfloat162 o = __floats2bfloat162_rn(
                    fmaxf(acc[mi][ni][2] + bb.x, 0.f),
                    fmaxf(acc[mi][ni][3] + bb.y, 0.f));
                *(__nv_bfloat162*)(out + (size_t)r2*HID + c) = o;
            }
        }
    }
}

// ---------------- multipool (bf16 input) ----------------
__global__ void pool_kernel(const int* __restrict__ batches){
    const __nv_bfloat16* h = g_BA;   // final layer output
    __shared__ int idxs[SUBSZ];
    int t = threadIdx.x, b = blockIdx.x;
    if (t < SUBSZ) idxs[t] = batches[b*SUBSZ + t];
    __syncthreads();
    float s = 0.f, mn = 3.4e38f, mx = -3.4e38f;
    #pragma unroll 8
    for (int m = 0; m < SUBSZ; m++){
        float v = __bfloat162float(h[(size_t)idxs[m]*HID + t]);
        s += v; mn = fminf(mn, v); mx = fmaxf(mx, v);
    }
    float* z = g_Z + (size_t)b*4*HID;
    z[t]         = s;
    z[HID + t]   = s * (1.0f/SUBSZ);
    z[2*HID + t] = mn;
    z[3*HID + t] = mx;
}

// ---------------- readout + BCE ----------------
__global__ void zero_out(float* out){
    if (threadIdx.x == 0 && blockIdx.x == 0) out[0] = 0.f;
}

__global__ __launch_bounds__(256)
void readout8(const float* __restrict__ Wr1, const float* __restrict__ br1,
              const float* __restrict__ Wr2, const float* __restrict__ br2,
              const float* __restrict__ labels, float* out){
    const int b0 = blockIdx.x*8;
    __shared__ float z[8*4*HID];
    int t = threadIdx.x;
    const float4* zg = (const float4*)(g_Z + (size_t)b0*4*HID);
    #pragma unroll
    for (int j = t; j < 8*4*HID/4; j += 256)
        ((float4*)z)[j] = zg[j];
    __syncthreads();

    float bb = br1[t];
    float acc[8];
    #pragma unroll
    for (int j=0;j<8;j++) acc[j] = bb;

    #pragma unroll 8
    for (int k=0;k<4*HID;k++){
        float w = Wr1[(size_t)k*HID + t];
        #pragma unroll
        for (int j=0;j<8;j++) acc[j] += z[j*4*HID + k]*w;
    }
    __syncthreads();
    float wr2 = Wr2[t];
    #pragma unroll
    for (int j=0;j<8;j++) z[j*HID + t] = fmaxf(acc[j], 0.f)*wr2;
    __syncthreads();

    int w = t >> 5, lane = t & 31;
    float s = 0.f;
    #pragma unroll
    for (int q=0;q<8;q++) s += z[w*HID + lane + q*32];
    #pragma unroll
    for (int off=16; off>0; off>>=1) s += __shfl_xor_sync(0xffffffffu, s, off);
    if (lane == 0){
        float p = s + br2[0];
        float l = labels[b0 + w];
        float term = fmaxf(p, 0.f) - p*l + log1pf(expf(-fabsf(p)));
        atomicAdd(out, term * (1.0f/NSUB));
    }
}

// ---------------- launch ----------------
static cudaStream_t g_s2 = nullptr;
static cudaEvent_t  g_evFork = nullptr, g_evJoin = nullptr;

extern "C" void kernel_launch(void* const* d_in, const int* in_sizes, int n_in,
                              void* d_out, int out_size){
    const float* x       = (const float*)d_in[0];
    const int*   esrc    = (const int*)  d_in[1];
    const int*   edst    = (const int*)  d_in[2];
    const float* ew      = (const float*)d_in[3];
    const int*   batches = (const int*)  d_in[4];
    const float* labels  = (const float*)d_in[6];
    const float* W0      = (const float*)d_in[7];
    const float* b0      = (const float*)d_in[8];
    const float* W1      = (const float*)d_in[9];
    const float* b1      = (const float*)d_in[10];
    const float* W2      = (const float*)d_in[11];
    const float* b2      = (const float*)d_in[12];
    const float* eps     = (const float*)d_in[13];
    const float* Wr1     = (const float*)d_in[14];
    const float* br1     = (const float*)d_in[15];
    const float* Wr2     = (const float*)d_in[16];
    const float* br2     = (const float*)d_in[17];
    float* out = (float*)d_out;

    if (!g_s2){
        cudaStreamCreateWithFlags(&g_s2, cudaStreamNonBlocking);
        cudaEventCreateWithFlags(&g_evFork, cudaEventDisableTiming);
        cudaEventCreateWithFlags(&g_evJoin, cudaEventDisableTiming);
    }

    cudaEventRecord(g_evFork, 0);
    cudaStreamWaitEvent(g_s2, g_evFork, 0);

    // main stream: input prep
    build_h0<<<4096, 256>>>(x);
    scatter_batch<<<(MTOT+255)/256, 256>>>(batches);
    build_w0p<<<(K0*HID+255)/256, 256>>>(W0);

    // side stream: CSR build (by dst)
    zero_degcur<<<(NN+255)/256, 256, 0, g_s2>>>();
    hist_dst<<<(NE+255)/256, 256, 0, g_s2>>>(edst);
    scan_block<<<NBLK, SCAN_B, 0, g_s2>>>();
    scan_bsums<<<1, 256, 0, g_s2>>>();
    scan_add<<<NBLK, SCAN_B, 0, g_s2>>>();
    csr_scatter<<<(NE+255)/256, 256, 0, g_s2>>>(esrc, edst, ew);

    cudaEventRecord(g_evJoin, g_s2);
    cudaStreamWaitEvent(0, g_evJoin, 0);

    dim3 gemmGrid(2, (NN+127)/128);
    const int gatherGrid = (NN+7)/8;

    // layer 0
    csr_gather<<<gatherGrid, 256>>>(0, eps, 0, K0, 33, 40);
    gemm_mma<K0><<<gemmGrid, 256>>>(nullptr, 1, b0, 1);

    // layer 1
    csr_gather<<<gatherGrid, 256>>>(1, eps, 1, HID, 64, 64);
    gemm_mma<HID><<<gemmGrid, 256>>>(W1, 0, b1, 2);

    // layer 2
    csr_gather<<<gatherGrid, 256>>>(2, eps, 2, HID, 64, 64);
    gemm_mma<HID><<<gemmGrid, 256>>>(W2, 0, b2, 1);

    pool_kernel<<<NSUB, HID>>>(batches);
    zero_out<<<1, 32>>>(out);
    readout8<<<NSUB/8, 256>>>(Wr1, br1, Wr2, br2, labels, out);
}

// round 9
// speedup vs baseline: 2.8266x; 1.0445x over previous
#include <cuda_runtime.h>
#include <cuda_bf16.h>
#include <cuda_fp16.h>
#include <math.h>
#include <stdint.h>

#define NN    50000
#define FEAT  128
#define HID   256
#define K0    160        // layer-0 K (129 live -> 132 used) padded to 160
#define NE    800000
#define NSUB  512
#define SUBSZ 64
#define MTOT  (NSUB*SUBSZ)

#define SCAN_B 256
#define NBLK   ((NN + SCAN_B - 1) / SCAN_B)   // 196

// ---------------- scratch (device globals; no allocation allowed) ----------------
__device__ __align__(16) __half         g_MSG[NN*HID];   // fp16 GEMM A (160-col view for L0)
__device__ __align__(16) __nv_bfloat16  g_B0 [NN*K0];    // bf16 h0
__device__ __align__(16) __nv_bfloat16  g_BA [NN*HID];   // bf16 h (layers)
__device__ __align__(16) __nv_bfloat16  g_BB [NN*HID];
__device__ __align__(16) __half         g_W0h[K0*HID];   // fp16 zero-padded W0
__device__ __align__(16) __half         g_W1h[HID*HID];
__device__ __align__(16) __half         g_W2h[HID*HID];
__device__ __align__(16) float          g_Z  [NSUB*4*HID];
// CSR scratch
__device__ int   g_deg [NN];
__device__ int   g_cur [NN];
__device__ int   g_off [NN+1];
__device__ int   g_bsum[NBLK];
__device__ int   g_csrc[NE];
__device__ float g_cw  [NE];

__device__ __forceinline__ __nv_bfloat16* gbuf16(int id){
    switch(id){
        case 0: return g_B0;
        case 1: return g_BA;
        default: return g_BB;
    }
}

// ---------------- setup ----------------
__global__ void build_h0(const float* __restrict__ x){
    int idx = blockIdx.x*blockDim.x + threadIdx.x;
    const int total = NN*K0;
    for (; idx < total; idx += gridDim.x*blockDim.x){
        int i = idx / K0;
        int c = idx - i*K0;
        g_B0[idx] = (c < FEAT) ? __float2bfloat16(x[i*FEAT + c]) : __float2bfloat16(0.f);
    }
}

__global__ void scatter_batch(const int* __restrict__ batches){
    int m = blockIdx.x*blockDim.x + threadIdx.x;
    if (m < MTOT) g_B0[(size_t)batches[m]*K0 + FEAT] = __float2bfloat16(1.0f);
}

__global__ void build_w0h(const float* __restrict__ W0){
    int idx = blockIdx.x*blockDim.x + threadIdx.x;
    if (idx < K0*HID){
        int r = idx / HID;
        int c = idx - r*HID;
        g_W0h[idx] = (r < FEAT+1) ? __float2half(W0[r*HID + c]) : __float2half(0.f);
    }
}

__global__ void build_wh(const float* __restrict__ W, int sel){
    __half* dst = (sel == 1) ? g_W1h : g_W2h;
    int i = blockIdx.x*blockDim.x + threadIdx.x;
    if (i < HID*HID) dst[i] = __float2half(W[i]);
}

// ---------------- CSR build ----------------
__global__ void zero_degcur(){
    int i = blockIdx.x*blockDim.x + threadIdx.x;
    if (i < NN){ g_deg[i] = 0; g_cur[i] = 0; }
}

__global__ void hist_dst(const int* __restrict__ dst){
    int e = blockIdx.x*blockDim.x + threadIdx.x;
    if (e < NE) atomicAdd(&g_deg[dst[e]], 1);
}

__global__ void scan_block(){
    __shared__ int sh[SCAN_B];
    int i = blockIdx.x*SCAN_B + threadIdx.x;
    int v = (i < NN) ? g_deg[i] : 0;
    sh[threadIdx.x] = v;
    __syncthreads();
    #pragma unroll
    for (int off = 1; off < SCAN_B; off <<= 1){
        int add = (threadIdx.x >= off) ? sh[threadIdx.x - off] : 0;
        __syncthreads();
        sh[threadIdx.x] += add;
        __syncthreads();
    }
    if (i < NN) g_off[i] = sh[threadIdx.x] - v;
    if (threadIdx.x == SCAN_B-1) g_bsum[blockIdx.x] = sh[SCAN_B-1];
}

__global__ void scan_bsums(){
    __shared__ int sh[256];
    int t = threadIdx.x;
    int v = (t < NBLK) ? g_bsum[t] : 0;
    sh[t] = v;
    __syncthreads();
    #pragma unroll
    for (int off = 1; off < 256; off <<= 1){
        int add = (t >= off) ? sh[t - off] : 0;
        __syncthreads();
        sh[t] += add;
        __syncthreads();
    }
    if (t < NBLK) g_bsum[t] = sh[t] - v;
}

__global__ void scan_add(){
    int i = blockIdx.x*SCAN_B + threadIdx.x;
    if (i < NN) g_off[i] += g_bsum[blockIdx.x];
    if (i == 0) g_off[NN] = NE;
}

__global__ void csr_scatter(const int* __restrict__ src, const int* __restrict__ dst,
                            const float* __restrict__ ew){
    int e = blockIdx.x*blockDim.x + threadIdx.x;
    if (e < NE){
        int d = dst[e];
        int pos = g_off[d] + atomicAdd(&g_cur[d], 1);
        g_csrc[pos] = src[e];
        g_cw[pos]   = ew[e];
    }
}

// ---------------- gather (bf16 inputs, f32 accumulate, fp16 output) ----------------
__device__ __forceinline__ void facc(float4& a, float w, uint2 u){
    float2 f0 = __bfloat1622float2(*(__nv_bfloat162*)&u.x);
    float2 f1 = __bfloat1622float2(*(__nv_bfloat162*)&u.y);
    a.x += w*f0.x; a.y += w*f0.y; a.z += w*f1.x; a.w += w*f1.y;
}
__device__ __forceinline__ uint2 f4toh4(float4 a){
    __half2 lo = __floats2half2_rn(a.x, a.y);
    __half2 hi = __floats2half2_rn(a.z, a.w);
    return make_uint2(*(uint32_t*)&lo, *(uint32_t*)&hi);
}

__global__ __launch_bounds__(256)
void csr_gather(int hsel, const float* __restrict__ eps, int ei, int ld, int w4r, int w4p){
    const __nv_bfloat16* h = gbuf16(hsel);
    int n = blockIdx.x*8 + (threadIdx.x >> 5);
    if (n >= NN) return;
    int lane = threadIdx.x & 31;
    int s0 = g_off[n], s1 = g_off[n+1];

    const bool a0 = (lane      < w4r);
    const bool a1 = (lane + 32 < w4r);
    float4 acc0 = make_float4(0.f,0.f,0.f,0.f);
    float4 acc1 = make_float4(0.f,0.f,0.f,0.f);

    int e = s0;
    for (; e + 4 <= s1; e += 4){
        int   si[4]; float wi[4];
        #pragma unroll
        for (int j=0;j<4;j++){
            si[j] = __ldg(&g_csrc[e+j]);
            wi[j] = __ldg(&g_cw[e+j]);
        }
        uint2 u0[4], u1[4];
        #pragma unroll
        for (int j=0;j<4;j++){
            const uint2* hs = (const uint2*)(h + (size_t)si[j]*ld);
            if (a0) u0[j] = __ldg(&hs[lane]);
            if (a1) u1[j] = __ldg(&hs[lane+32]);
        }
        #pragma unroll
        for (int j=0;j<4;j++){
            if (a0) facc(acc0, wi[j], u0[j]);
            if (a1) facc(acc1, wi[j], u1[j]);
        }
    }
    for (; e < s1; e++){
        int   s = __ldg(&g_csrc[e]);
        float w = __ldg(&g_cw[e]);
        const uint2* hs = (const uint2*)(h + (size_t)s*ld);
        if (a0){ uint2 u = __ldg(&hs[lane]);    facc(acc0, w, u); }
        if (a1){ uint2 u = __ldg(&hs[lane+32]); facc(acc1, w, u); }
    }

    const float ep = 1.0f + eps[ei];
    const uint2* hn = (const uint2*)(h + (size_t)n*ld);
    uint2* mrow = (uint2*)(g_MSG + (size_t)n*ld);
    if (a0){
        uint2 u = __ldg(&hn[lane]);
        facc(acc0, ep, u);
        mrow[lane] = f4toh4(acc0);
    }
    if (a1){
        uint2 u = __ldg(&hn[lane+32]);
        facc(acc1, ep, u);
        mrow[lane+32] = f4toh4(acc1);
    } else if (lane + 32 < w4p){
        mrow[lane+32] = make_uint2(0u, 0u);
    }
}

// ---------------- tensor-core GIN GEMM: outb16 = relu(MSG @ W + b) ------
// pure fp16, BK=32, cp.async double-buffered, 1 sync per kstep.
__device__ __forceinline__ uint32_t sptr(const void* p){
    return (uint32_t)__cvta_generic_to_shared(p);
}
__device__ __forceinline__ void cpa16(uint32_t smem, const void* g, int nbytes){
    asm volatile("cp.async.cg.shared.global [%0], [%1], 16, %2;"
                 :: "r"(smem), "l"(g), "r"(nbytes) : "memory");
}
#define CP_COMMIT() asm volatile("cp.async.commit_group;" ::: "memory")
#define CP_WAIT0()  asm volatile("cp.async.wait_group 0;" ::: "memory")

__device__ __forceinline__ void ldsm4(uint32_t& r0,uint32_t& r1,uint32_t& r2,uint32_t& r3, uint32_t a){
    asm volatile("ldmatrix.sync.aligned.m8n8.x4.shared.b16 {%0,%1,%2,%3},[%4];"
                 : "=r"(r0),"=r"(r1),"=r"(r2),"=r"(r3) : "r"(a));
}
__device__ __forceinline__ void ldsm4t(uint32_t& r0,uint32_t& r1,uint32_t& r2,uint32_t& r3, uint32_t a){
    asm volatile("ldmatrix.sync.aligned.m8n8.x4.trans.shared.b16 {%0,%1,%2,%3},[%4];"
                 : "=r"(r0),"=r"(r1),"=r"(r2),"=r"(r3) : "r"(a));
}
__device__ __forceinline__ void mma16816h(float* c, const uint32_t* a, uint32_t b0, uint32_t b1){
    asm volatile("mma.sync.aligned.m16n8k16.row.col.f32.f16.f16.f32 "
                 "{%0,%1,%2,%3},{%4,%5,%6,%7},{%8,%9},{%0,%1,%2,%3};"
                 : "+f"(c[0]),"+f"(c[1]),"+f"(c[2]),"+f"(c[3])
                 : "r"(a[0]),"r"(a[1]),"r"(a[2]),"r"(a[3]),"r"(b0),"r"(b1));
}

#define ALD2 40    // Ash row stride (halves), BK=32 + pad 8
#define BLD  136   // Bsh row stride (halves)

template<int K>
__global__ __launch_bounds__(256)
void gemm_mma(int wsel, const float* __restrict__ bias, int osel){
    const __half* A  = g_MSG;
    const __half* Wh = (wsel == 0) ? g_W0h : (wsel == 1) ? g_W1h : g_W2h;
    __nv_bfloat16* out = gbuf16(osel);

    __shared__ __half Ash[2][128*ALD2];
    __shared__ __half Bsh[2][32*BLD];

    const int t = threadIdx.x;
    const int warp = t >> 5, lane = t & 31;
    const int wm = warp >> 2, wn = warp & 3;
    const int row0 = blockIdx.y*128, col0 = blockIdx.x*128;

    float acc[4][4][4];
    #pragma unroll
    for (int i=0;i<4;i++)
        #pragma unroll
        for (int j=0;j<4;j++)
            #pragma unroll
            for (int q=0;q<4;q++) acc[i][j][q]=0.f;

    auto prefetch = [&](int ks, int buf){
        const int k0 = ks*32;
        // A: 128 rows x 32 halves (64B) = 512 x 16B chunks
        #pragma unroll
        for (int s=0;s<2;s++){
            int c = t + s*256;
            int r = c >> 2, seg = c & 3;
            int gr = row0 + r;
            uint32_t dst = sptr(&Ash[buf][r*ALD2 + seg*8]);
            const void* src = A + (size_t)gr*K + k0 + seg*8;
            cpa16(dst, src, (gr < NN) ? 16 : 0);
        }
        // B: 32 rows x 128 halves (256B) = 512 x 16B chunks
        #pragma unroll
        for (int s=0;s<2;s++){
            int c = t + s*256;
            int r = c >> 4, seg = c & 15;
            uint32_t dst = sptr(&Bsh[buf][r*BLD + seg*8]);
            const void* src = Wh + (size_t)(k0 + r)*HID + col0 + seg*8;
            cpa16(dst, src, 16);
        }
    };

    auto compute = [&](int buf){
        #pragma unroll
        for (int h=0; h<2; h++){
            const int arow = wm*64 + (lane & 15);
            const int acol = h*16 + (lane >> 4)*8;
            uint32_t aA = sptr(&Ash[buf][0]) + (uint32_t)((arow*ALD2 + acol)*2);
            const int brow = h*16 + (lane & 15);
            const int bcol = wn*32 + (lane >> 4)*8;
            uint32_t bA = sptr(&Bsh[buf][0]) + (uint32_t)((brow*BLD + bcol)*2);

            uint32_t A_[4][4], B[4][2];
            #pragma unroll
            for (int mi=0; mi<4; mi++)
                ldsm4(A_[mi][0],A_[mi][1],A_[mi][2],A_[mi][3], aA + (uint32_t)(mi*16*ALD2*2));
            #pragma unroll
            for (int np=0; np<2; np++)
                ldsm4t(B[2*np][0],B[2*np][1],B[2*np+1][0],B[2*np+1][1],
                       bA + (uint32_t)(np*16*2));
            #pragma unroll
            for (int mi=0; mi<4; mi++)
                #pragma unroll
                for (int ni=0; ni<4; ni++)
                    mma16816h(acc[mi][ni], A_[mi], B[ni][0], B[ni][1]);
        }
    };

    const int KS = K/32;
    prefetch(0, 0); CP_COMMIT();
    int buf = 0;
    for (int ks=0; ks<KS; ks++){
        CP_WAIT0();
        __syncthreads();
        if (ks+1 < KS){ prefetch(ks+1, buf^1); CP_COMMIT(); }
        compute(buf);
        buf ^= 1;
    }

    // epilogue: bias + relu, bf16 stores
    const int gid = lane >> 2, tig = lane & 3;
    #pragma unroll
    for (int ni=0; ni<4; ni++){
        int c = col0 + wn*32 + ni*8 + tig*2;
        float2 bb = *(const float2*)(bias + c);
        #pragma unroll
        for (int mi=0; mi<4; mi++){
            int r = row0 + wm*64 + mi*16 + gid;
            if (r < NN){
                __nv_bfloat162 o = __floats2bfloat162_rn(
                    fmaxf(acc[mi][ni][0] + bb.x, 0.f),
                    fmaxf(acc[mi][ni][1] + bb.y, 0.f));
                *(__nv_bfloat162*)(out + (size_t)r*HID + c) = o;
            }
            int r2 = r + 8;
            if (r2 < NN){
                __nv_bfloat162 o = __floats2bfloat162_rn(
                    fmaxf(acc[mi][ni][2] + bb.x, 0.f),
                    fmaxf(acc[mi][ni][3] + bb.y, 0.f));
                *(__nv_bfloat162*)(out + (size_t)r2*HID + c) = o;
            }
        }
    }
}

// ---------------- multipool (bf16 input) ----------------
__global__ void pool_kernel(const int* __restrict__ batches){
    const __nv_bfloat16* h = g_BA;   // final layer output
    __shared__ int idxs[SUBSZ];
    int t = threadIdx.x, b = blockIdx.x;
    if (t < SUBSZ) idxs[t] = batches[b*SUBSZ + t];
    __syncthreads();
    float s = 0.f, mn = 3.4e38f, mx = -3.4e38f;
    #pragma unroll 8
    for (int m = 0; m < SUBSZ; m++){
        float v = __bfloat162float(h[(size_t)idxs[m]*HID + t]);
        s += v; mn = fminf(mn, v); mx = fmaxf(mx, v);
    }
    float* z = g_Z + (size_t)b*4*HID;
    z[t]         = s;
    z[HID + t]   = s * (1.0f/SUBSZ);
    z[2*HID + t] = mn;
    z[3*HID + t] = mx;
}

// ---------------- readout + BCE ----------------
__global__ void zero_out(float* out){
    if (threadIdx.x == 0 && blockIdx.x == 0) out[0] = 0.f;
}

__global__ __launch_bounds__(256)
void readout8(const float* __restrict__ Wr1, const float* __restrict__ br1,
              const float* __restrict__ Wr2, const float* __restrict__ br2,
              const float* __restrict__ labels, float* out){
    const int b0 = blockIdx.x*8;
    __shared__ float z[8*4*HID];
    int t = threadIdx.x;
    const float4* zg = (const float4*)(g_Z + (size_t)b0*4*HID);
    #pragma unroll
    for (int j = t; j < 8*4*HID/4; j += 256)
        ((float4*)z)[j] = zg[j];
    __syncthreads();

    float bb = br1[t];
    float acc[8];
    #pragma unroll
    for (int j=0;j<8;j++) acc[j] = bb;

    #pragma unroll 8
    for (int k=0;k<4*HID;k++){
        float w = Wr1[(size_t)k*HID + t];
        #pragma unroll
        for (int j=0;j<8;j++) acc[j] += z[j*4*HID + k]*w;
    }
    __syncthreads();
    float wr2 = Wr2[t];
    #pragma unroll
    for (int j=0;j<8;j++) z[j*HID + t] = fmaxf(acc[j], 0.f)*wr2;
    __syncthreads();

    int w = t >> 5, lane = t & 31;
    float s = 0.f;
    #pragma unroll
    for (int q=0;q<8;q++) s += z[w*HID + lane + q*32];
    #pragma unroll
    for (int off=16; off>0; off>>=1) s += __shfl_xor_sync(0xffffffffu, s, off);
    if (lane == 0){
        float p = s + br2[0];
        float l = labels[b0 + w];
        float term = fmaxf(p, 0.f) - p*l + log1pf(expf(-fabsf(p)));
        atomicAdd(out, term * (1.0f/NSUB));
    }
}

// ---------------- launch ----------------
static cudaStream_t g_s2 = nullptr;
static cudaEvent_t  g_evFork = nullptr, g_evJoin = nullptr;

extern "C" void kernel_launch(void* const* d_in, const int* in_sizes, int n_in,
                              void* d_out, int out_size){
    const float* x       = (const float*)d_in[0];
    const int*   esrc    = (const int*)  d_in[1];
    const int*   edst    = (const int*)  d_in[2];
    const float* ew      = (const float*)d_in[3];
    const int*   batches = (const int*)  d_in[4];
    const float* labels  = (const float*)d_in[6];
    const float* W0      = (const float*)d_in[7];
    const float* b0      = (const float*)d_in[8];
    const float* W1      = (const float*)d_in[9];
    const float* b1      = (const float*)d_in[10];
    const float* W2      = (const float*)d_in[11];
    const float* b2      = (const float*)d_in[12];
    const float* eps     = (const float*)d_in[13];
    const float* Wr1     = (const float*)d_in[14];
    const float* br1     = (const float*)d_in[15];
    const float* Wr2     = (const float*)d_in[16];
    const float* br2     = (const float*)d_in[17];
    float* out = (float*)d_out;

    if (!g_s2){
        cudaStreamCreateWithFlags(&g_s2, cudaStreamNonBlocking);
        cudaEventCreateWithFlags(&g_evFork, cudaEventDisableTiming);
        cudaEventCreateWithFlags(&g_evJoin, cudaEventDisableTiming);
    }

    cudaEventRecord(g_evFork, 0);
    cudaStreamWaitEvent(g_s2, g_evFork, 0);

    // main stream: input prep + weight conversion
    build_h0<<<4096, 256>>>(x);
    scatter_batch<<<(MTOT+255)/256, 256>>>(batches);
    build_w0h<<<(K0*HID+255)/256, 256>>>(W0);
    build_wh<<<(HID*HID+255)/256, 256>>>(W1, 1);
    build_wh<<<(HID*HID+255)/256, 256>>>(W2, 2);

    // side stream: CSR build (by dst)
    zero_degcur<<<(NN+255)/256, 256, 0, g_s2>>>();
    hist_dst<<<(NE+255)/256, 256, 0, g_s2>>>(edst);
    scan_block<<<NBLK, SCAN_B, 0, g_s2>>>();
    scan_bsums<<<1, 256, 0, g_s2>>>();
    scan_add<<<NBLK, SCAN_B, 0, g_s2>>>();
    csr_scatter<<<(NE+255)/256, 256, 0, g_s2>>>(esrc, edst, ew);

    cudaEventRecord(g_evJoin, g_s2);
    cudaStreamWaitEvent(0, g_evJoin, 0);

    dim3 gemmGrid(2, (NN+127)/128);
    const int gatherGrid = (NN+7)/8;

    // layer 0
    csr_gather<<<gatherGrid, 256>>>(0, eps, 0, K0, 33, 40);
    gemm_mma<K0><<<gemmGrid, 256>>>(0, b0, 1);

    // layer 1
    csr_gather<<<gatherGrid, 256>>>(1, eps, 1, HID, 64, 64);
    gemm_mma<HID><<<gemmGrid, 256>>>(1, b1, 2);

    // layer 2
    csr_gather<<<gatherGrid, 256>>>(2, eps, 2, HID, 64, 64);
    gemm_mma<HID><<<gemmGrid, 256>>>(2, b2, 1);

    pool_kernel<<<NSUB, HID>>>(batches);
    zero_out<<<1, 32>>>(out);
    readout8<<<NSUB/8, 256>>>(Wr1, br1, Wr2, br2, labels, out);
}